// round 12
// baseline (speedup 1.0000x reference)
#include <cuda_runtime.h>
#include <cuda_bf16.h>
#include <math.h>
#include <stdint.h>

// Problem constants
#define Bsz   2
#define Ssz   2048
#define Dsz   1024
#define Hsz   16
#define HDsz  64
#define DFFsz 4096
#define ROWS  (Bsz*Ssz)
#define EPSLN 1e-5f

// ---------------- scratch (device globals) ---------------------------------
__device__ float g_x1 [ROWS*Dsz];

__device__ __nv_bfloat16 g_xnh [ROWS*Dsz],  g_xnl [ROWS*Dsz];
__device__ __nv_bfloat16 g_xn2h[ROWS*Dsz],  g_xn2l[ROWS*Dsz];
__device__ __nv_bfloat16 g_ctxh[ROWS*Dsz],  g_ctxl[ROWS*Dsz];
__device__ __nv_bfloat16 g_hh  [ROWS*DFFsz], g_hl [ROWS*DFFsz];

__device__ __nv_bfloat16 g_qb[ROWS*Dsz];
__device__ __nv_bfloat16 g_kb[ROWS*Dsz];
__device__ __nv_bfloat16 g_vt[Bsz*Hsz*HDsz*Ssz];

__device__ __nv_bfloat16 g_wqkv_h[3*Dsz*Dsz], g_wqkv_l[3*Dsz*Dsz];
__device__ __nv_bfloat16 g_wo_h[Dsz*Dsz],  g_wo_l[Dsz*Dsz];
__device__ __nv_bfloat16 g_w1_h[Dsz*DFFsz], g_w1_l[Dsz*DFFsz];
__device__ __nv_bfloat16 g_w2_h[DFFsz*Dsz], g_w2_l[DFFsz*Dsz];

// ---------------- helpers ---------------------------------------------------
__device__ __forceinline__ uint32_t smem_u32(const void* p) {
    uint32_t a;
    asm("{ .reg .u64 t; cvta.to.shared.u64 t, %1; cvt.u32.u64 %0, t; }"
        : "=r"(a) : "l"(p));
    return a;
}
__device__ __forceinline__ void cpa16(uint32_t d, const void* s) {
    asm volatile("cp.async.cg.shared.global [%0], [%1], 16;" :: "r"(d), "l"(s));
}
#define CPA_COMMIT asm volatile("cp.async.commit_group;" ::: "memory")
#define CPA_WAIT(n) asm volatile("cp.async.wait_group %0;" :: "n"(n) : "memory")

__device__ __forceinline__ void ldm4(uint32_t* d, uint32_t a) {
    asm volatile("ldmatrix.sync.aligned.m8n8.x4.shared.b16 {%0,%1,%2,%3}, [%4];"
        : "=r"(d[0]), "=r"(d[1]), "=r"(d[2]), "=r"(d[3]) : "r"(a));
}
__device__ __forceinline__ float gelu_exact(float x) {
    return 0.5f * x * (1.0f + erff(x * 0.70710678118654752440f));
}
__device__ __forceinline__ uint32_t packbf(float x, float y) {
    uint32_t lo = __bfloat16_as_ushort(__float2bfloat16_rn(x));
    uint32_t hi = __bfloat16_as_ushort(__float2bfloat16_rn(y));
    return lo | (hi << 16);
}
__device__ __forceinline__ void mma16816(float* c, const uint32_t* a, const uint32_t* b) {
    asm volatile(
        "mma.sync.aligned.m16n8k16.row.col.f32.bf16.bf16.f32 "
        "{%0,%1,%2,%3}, {%4,%5,%6,%7}, {%8,%9}, {%0,%1,%2,%3};"
        : "+f"(c[0]), "+f"(c[1]), "+f"(c[2]), "+f"(c[3])
        : "r"(a[0]), "r"(a[1]), "r"(a[2]), "r"(a[3]), "r"(b[0]), "r"(b[1]));
}

__device__ __forceinline__ float block_sum(float v) {
    __shared__ float sh[8];
    int lane = threadIdx.x & 31, w = threadIdx.x >> 5;
    #pragma unroll
    for (int o = 16; o > 0; o >>= 1) v += __shfl_down_sync(0xffffffffu, v, o);
    if (!lane) sh[w] = v;
    __syncthreads();
    if (w == 0) {
        float t = (lane < 8) ? sh[lane] : 0.f;
        #pragma unroll
        for (int o = 4; o > 0; o >>= 1) t += __shfl_down_sync(0xffu, t, o);
        if (lane == 0) sh[0] = t;
    }
    __syncthreads();
    float r = sh[0];
    __syncthreads();
    return r;
}

// ---------------- layernorm -> bf16 hi/lo ----------------------------------
__global__ __launch_bounds__(256) void ln_bf_kernel(
    const float* __restrict__ x, const float* __restrict__ g,
    const float* __restrict__ b,
    __nv_bfloat16* __restrict__ oh, __nv_bfloat16* __restrict__ ol)
{
    int row = blockIdx.x, tid = threadIdx.x;
    const float* xr = x + (long long)row * Dsz;
    float4 v = *reinterpret_cast<const float4*>(xr + tid * 4);
    float mu = block_sum(v.x + v.y + v.z + v.w) * (1.0f / Dsz);
    float d0 = v.x - mu, d1 = v.y - mu, d2 = v.z - mu, d3 = v.w - mu;
    float var = block_sum(d0*d0 + d1*d1 + d2*d2 + d3*d3) * (1.0f / Dsz);
    float inv = rsqrtf(var + EPSLN);
    float4 gg = *reinterpret_cast<const float4*>(g + tid * 4);
    float4 bb = *reinterpret_cast<const float4*>(b + tid * 4);
    float o0 = d0 * inv * gg.x + bb.x;
    float o1 = d1 * inv * gg.y + bb.y;
    float o2 = d2 * inv * gg.z + bb.z;
    float o3 = d3 * inv * gg.w + bb.w;
    __nv_bfloat16 h0 = __float2bfloat16_rn(o0), h1 = __float2bfloat16_rn(o1);
    __nv_bfloat16 h2 = __float2bfloat16_rn(o2), h3 = __float2bfloat16_rn(o3);
    uint2 uh, ul;
    uh.x = (uint32_t)__bfloat16_as_ushort(h0) | ((uint32_t)__bfloat16_as_ushort(h1) << 16);
    uh.y = (uint32_t)__bfloat16_as_ushort(h2) | ((uint32_t)__bfloat16_as_ushort(h3) << 16);
    ul.x = packbf(o0 - __bfloat162float(h0), o1 - __bfloat162float(h1));
    ul.y = packbf(o2 - __bfloat162float(h2), o3 - __bfloat162float(h3));
    long long off = (long long)row * Dsz + tid * 4;
    *reinterpret_cast<uint2*>(oh + off) = uh;
    *reinterpret_cast<uint2*>(ol + off) = ul;
}

// ---------------- merged weight transpose + bf16 hi/lo split ---------------
__global__ __launch_bounds__(256) void wconv_all_kernel(
    const float* __restrict__ Wq, const float* __restrict__ Wk,
    const float* __restrict__ Wv, const float* __restrict__ Wo,
    const float* __restrict__ W1, const float* __restrict__ W2,
    __nv_bfloat16* __restrict__ wqkvh, __nv_bfloat16* __restrict__ wqkvl,
    __nv_bfloat16* __restrict__ woh,   __nv_bfloat16* __restrict__ wol,
    __nv_bfloat16* __restrict__ w1h,   __nv_bfloat16* __restrict__ w1l,
    __nv_bfloat16* __restrict__ w2h,   __nv_bfloat16* __restrict__ w2l)
{
    int idx = blockIdx.x;
    const float* W; __nv_bfloat16 *Th, *Tl; int K, N, seg;
    if (idx < 4096) {
        K = Dsz; N = Dsz; seg = idx & 1023;
        int which = idx >> 10;
        if (which == 0) { W = Wq; Th = wqkvh;             Tl = wqkvl; }
        else if (which == 1) { W = Wk; Th = wqkvh + Dsz*Dsz;   Tl = wqkvl + Dsz*Dsz; }
        else if (which == 2) { W = Wv; Th = wqkvh + 2*Dsz*Dsz; Tl = wqkvl + 2*Dsz*Dsz; }
        else { W = Wo; Th = woh; Tl = wol; }
    } else if (idx < 8192) {
        K = Dsz; N = DFFsz; seg = idx - 4096; W = W1; Th = w1h; Tl = w1l;
    } else {
        K = DFFsz; N = Dsz; seg = idx - 8192; W = W2; Th = w2h; Tl = w2l;
    }
    int nBN = N / 32;
    int n0 = (seg % nBN) * 32, k0 = (seg / nBN) * 32;

    __shared__ float t[32][33];
    int tx = threadIdx.x & 31, ty = threadIdx.x >> 5;
    #pragma unroll
    for (int r = 0; r < 4; ++r)
        t[ty + r * 8][tx] = W[(size_t)(k0 + ty + r * 8) * N + n0 + tx];
    __syncthreads();
    #pragma unroll
    for (int r = 0; r < 4; ++r) {
        int n = n0 + ty + r * 8, k = k0 + tx;
        float w = t[tx][ty + r * 8];
        __nv_bfloat16 hi = __float2bfloat16_rn(w);
        __nv_bfloat16 lo = __float2bfloat16_rn(w - __bfloat162float(hi));
        Th[(size_t)n * K + k] = hi;
        Tl[(size_t)n * K + k] = lo;
    }
}

// ---------------- bf16x3 GEMM: 256x128 tile, 512 thr, 3-stage cp.async -----
// act: 0 = plain, 1 = gelu, 2 = fused QKV epilogue (rope->qb/kb, transpose->vt)
#define PADK     40
#define AH_OFF   0
#define AL_OFF   10240
#define BH_OFF   20480
#define BL_OFF   25600
#define SSTRIDE  30720                 // ushorts per stage (256+256+128+128 rows x 40)
#define BG_SMEM  (3 * SSTRIDE * 2)     // 184320 bytes

__global__ __launch_bounds__(512, 1) void bgemm(
    const __nv_bfloat16* __restrict__ Ah, const __nv_bfloat16* __restrict__ Al,
    const __nv_bfloat16* __restrict__ Bh, const __nv_bfloat16* __restrict__ Bl,
    float* __restrict__ C,
    __nv_bfloat16* __restrict__ Oh, __nv_bfloat16* __restrict__ Ol,
    int K, int N,
    const float* __restrict__ bias, const float* __restrict__ resid, int act,
    const float* __restrict__ fc, const float* __restrict__ fs,
    __nv_bfloat16* __restrict__ qb, __nv_bfloat16* __restrict__ kb,
    __nv_bfloat16* __restrict__ vt)
{
    extern __shared__ unsigned short sm[];
    uint32_t smB = smem_u32(sm);
    int tid = threadIdx.x, lane = tid & 31, wid = tid >> 5;   // wid 0..15
    int wr = wid >> 2, wc = wid & 3;                          // 4x4 warp grid
    int gid = lane >> 2, tig = lane & 3;
    int laneRow = lane & 7, lt = lane >> 3;
    int tileN = blockIdx.x * 128, tileM = blockIdx.y * 256;

    const __nv_bfloat16* Ahb = Ah + (size_t)tileM * K;
    const __nv_bfloat16* Alb = Al + (size_t)tileM * K;
    const __nv_bfloat16* Bhb = Bh + (size_t)tileN * K;
    const __nv_bfloat16* Blb = Bl + (size_t)tileN * K;

    float acc[4][4][4];
    #pragma unroll
    for (int mf = 0; mf < 4; ++mf)
        #pragma unroll
        for (int nf = 0; nf < 4; ++nf)
            #pragma unroll
            for (int i = 0; i < 4; ++i) acc[mf][nf][i] = 0.f;

    uint32_t aoff = (uint32_t)((wr * 64 + laneRow + ((lt & 1) ? 8 : 0)) * PADK
                               + ((lt & 2) ? 8 : 0));
    uint32_t boff = (uint32_t)((wc * 32 + laneRow + ((lt & 2) ? 8 : 0)) * PADK
                               + ((lt & 1) ? 8 : 0));

    // cp.async coords: A 256x32 (2 slots/thread/array), B 128x32 (1 slot)
    int aR0 = tid >> 2,  aC0 = tid & 3;        // rows 0..127
    int aR1 = aR0 + 128;                       // rows 128..255
    int bR  = tid >> 2,  bC = tid & 3;         // only tid<512: rows 0..127 via >>2
    // B has 512 slots total (128 rows x 4), exactly 1 per thread.

    int nCh = K >> 5;

    // issue one chunk's loads into stage st
    auto issue = [&](int chunk, int st) {
        uint32_t sb = smB + (uint32_t)st * (SSTRIDE * 2);
        int k0 = chunk << 5;
        uint32_t da0 = (uint32_t)(aR0 * PADK + aC0 * 8) * 2;
        uint32_t da1 = (uint32_t)(aR1 * PADK + aC0 * 8) * 2;
        size_t sa0 = (size_t)aR0 * K + k0 + aC0 * 8;
        size_t sa1 = (size_t)aR1 * K + k0 + aC0 * 8;
        cpa16(sb + AH_OFF*2 + da0, Ahb + sa0);
        cpa16(sb + AH_OFF*2 + da1, Ahb + sa1);
        cpa16(sb + AL_OFF*2 + da0, Alb + sa0);
        cpa16(sb + AL_OFF*2 + da1, Alb + sa1);
        uint32_t db = (uint32_t)(bR * PADK + bC * 8) * 2;
        size_t sbg = (size_t)bR * K + k0 + bC * 8;
        cpa16(sb + BH_OFF*2 + db, Bhb + sbg);
        cpa16(sb + BL_OFF*2 + db, Blb + sbg);
        CPA_COMMIT;
    };

    issue(0, 0);
    if (nCh > 1) issue(1, 1);

    for (int c = 0; c < nCh; ++c) {
        if (c < nCh - 1) { CPA_WAIT(1); } else { CPA_WAIT(0); }
        __syncthreads();
        if (c + 2 < nCh) issue(c + 2, (c + 2) % 3);

        uint32_t stb = smB + (uint32_t)(c % 3) * (SSTRIDE * 2);
        #pragma unroll
        for (int kk = 0; kk < 32; kk += 16) {
            uint32_t ah[4][4], al[4][4], bh[4][2], bl[4][2];
            #pragma unroll
            for (int mf = 0; mf < 4; ++mf) {
                uint32_t ad = stb + 2u * (aoff + (uint32_t)(mf * 16 * PADK + kk));
                ldm4(ah[mf], ad + 2u * AH_OFF);
                ldm4(al[mf], ad + 2u * AL_OFF);
            }
            #pragma unroll
            for (int np = 0; np < 2; ++np) {
                uint32_t bd = stb + 2u * (boff + (uint32_t)(np * 16 * PADK + kk));
                uint32_t t4[4];
                ldm4(t4, bd + 2u * BH_OFF);
                bh[2*np][0] = t4[0]; bh[2*np][1] = t4[1];
                bh[2*np+1][0] = t4[2]; bh[2*np+1][1] = t4[3];
                ldm4(t4, bd + 2u * BL_OFF);
                bl[2*np][0] = t4[0]; bl[2*np][1] = t4[1];
                bl[2*np+1][0] = t4[2]; bl[2*np+1][1] = t4[3];
            }
            #pragma unroll
            for (int mf = 0; mf < 4; ++mf)
                #pragma unroll
                for (int nf = 0; nf < 4; ++nf) {
                    mma16816(acc[mf][nf], ah[mf], bh[nf]);
                    mma16816(acc[mf][nf], ah[mf], bl[nf]);
                    mma16816(acc[mf][nf], al[mf], bh[nf]);
                }
        }
        __syncthreads();
    }

    // ---- epilogue ----
    if (act == 2) {
        // fused QKV: rope -> qb/kb, transpose -> vt. N == 3*Dsz.
        #pragma unroll
        for (int mf = 0; mf < 4; ++mf) {
            int row = tileM + wr * 64 + mf * 16 + gid;      // token row
            #pragma unroll
            for (int nf = 0; nf < 4; ++nf) {
                int col = tileN + wc * 32 + nf * 8 + 2 * tig;
                #pragma unroll
                for (int half = 0; half < 2; ++half) {
                    int r = row + half * 8;
                    float e = acc[mf][nf][2*half];
                    float o = acc[mf][nf][2*half + 1];
                    int srow = r & (Ssz - 1);
                    if (col < Dsz) {
                        int i = (col & 63) >> 1;
                        float cv = fc[srow * 32 + i], sv = fs[srow * 32 + i];
                        float r0 = (e * cv - o * sv) * 0.125f;
                        float r1 = (e * sv + o * cv) * 0.125f;
                        __nv_bfloat162 p;
                        p.x = __float2bfloat16_rn(r0); p.y = __float2bfloat16_rn(r1);
                        *reinterpret_cast<__nv_bfloat162*>(qb + (size_t)r * Dsz + col) = p;
                    } else if (col < 2 * Dsz) {
                        int cc = col - Dsz;
                        int i = (cc & 63) >> 1;
                        float cv = fc[srow * 32 + i], sv = fs[srow * 32 + i];
                        float r0 = e * cv - o * sv;
                        float r1 = e * sv + o * cv;
                        __nv_bfloat162 p;
                        p.x = __float2bfloat16_rn(r0); p.y = __float2bfloat16_rn(r1);
                        *reinterpret_cast<__nv_bfloat162*>(kb + (size_t)r * Dsz + cc) = p;
                    } else {
                        int cc = col - 2 * Dsz;
                        int h = cc >> 6, n = cc & 63;
                        int bh = (r >> 11) * Hsz + h;
                        size_t base = ((size_t)bh * HDsz) * Ssz + srow;
                        vt[base + (size_t)n * Ssz]       = __float2bfloat16_rn(e);
                        vt[base + (size_t)(n + 1) * Ssz] = __float2bfloat16_rn(o);
                    }
                }
            }
        }
        return;
    }

    #pragma unroll
    for (int mf = 0; mf < 4; ++mf) {
        int row = tileM + wr * 64 + mf * 16 + gid;
        #pragma unroll
        for (int nf = 0; nf < 4; ++nf) {
            int col = tileN + wc * 32 + nf * 8 + 2 * tig;
            float2 v0 = make_float2(acc[mf][nf][0], acc[mf][nf][1]);
            float2 v1 = make_float2(acc[mf][nf][2], acc[mf][nf][3]);
            if (bias) {
                float2 bv = *reinterpret_cast<const float2*>(bias + col);
                v0.x += bv.x; v0.y += bv.y;
                v1.x += bv.x; v1.y += bv.y;
            }
            if (act == 1) {
                v0.x = gelu_exact(v0.x); v0.y = gelu_exact(v0.y);
                v1.x = gelu_exact(v1.x); v1.y = gelu_exact(v1.y);
            }
            size_t i0 = (size_t)row * N + col;
            size_t i1 = (size_t)(row + 8) * N + col;
            if (resid) {
                float2 r0 = *reinterpret_cast<const float2*>(resid + i0);
                float2 r1 = *reinterpret_cast<const float2*>(resid + i1);
                v0.x += r0.x; v0.y += r0.y;
                v1.x += r1.x; v1.y += r1.y;
            }
            if (C) {
                *reinterpret_cast<float2*>(C + i0) = v0;
                *reinterpret_cast<float2*>(C + i1) = v1;
            }
            if (Oh) {
                __nv_bfloat16 h0 = __float2bfloat16_rn(v0.x), h1 = __float2bfloat16_rn(v0.y);
                __nv_bfloat16 h2 = __float2bfloat16_rn(v1.x), h3 = __float2bfloat16_rn(v1.y);
                uint32_t uh0 = (uint32_t)__bfloat16_as_ushort(h0) | ((uint32_t)__bfloat16_as_ushort(h1) << 16);
                uint32_t uh1 = (uint32_t)__bfloat16_as_ushort(h2) | ((uint32_t)__bfloat16_as_ushort(h3) << 16);
                uint32_t ul0 = packbf(v0.x - __bfloat162float(h0), v0.y - __bfloat162float(h1));
                uint32_t ul1 = packbf(v1.x - __bfloat162float(h2), v1.y - __bfloat162float(h3));
                *reinterpret_cast<uint32_t*>(Oh + i0) = uh0;
                *reinterpret_cast<uint32_t*>(Oh + i1) = uh1;
                *reinterpret_cast<uint32_t*>(Ol + i0) = ul0;
                *reinterpret_cast<uint32_t*>(Ol + i1) = ul1;
            }
        }
    }
}

// ---------------- fused flash attention (2 CTAs/SM) -------------------------
#define FQS 72
#define FVS 136
#define FQ_OFF 0
#define FK_OFF 9216
#define FV_OFF (9216 + 2*9216)
#define FSM_BYTES ((FV_OFF + 2*8704) * 2)

__global__ __launch_bounds__(256, 2) void flash_kernel(
    const __nv_bfloat16* __restrict__ Qb, const __nv_bfloat16* __restrict__ Kb,
    const __nv_bfloat16* __restrict__ Vt,
    __nv_bfloat16* __restrict__ ctxh, __nv_bfloat16* __restrict__ ctxl)
{
    extern __shared__ unsigned short fsm[];
    uint32_t smB = smem_u32(fsm);
    int tid = threadIdx.x, lane = tid & 31, w = tid >> 5;
    int gid = lane >> 2, tig = lane & 3;
    int laneRow = lane & 7, lt = lane >> 3;
    int tq = blockIdx.x, bh = blockIdx.y;
    int b = bh >> 4, h = bh & 15;

    size_t qRow0 = (size_t)b * Ssz + tq * 128;
    const __nv_bfloat16* Qg = Qb + qRow0 * Dsz + h * HDsz;
    const __nv_bfloat16* Kg = Kb + ((size_t)b * Ssz) * Dsz + h * HDsz;
    const __nv_bfloat16* Vg = Vt + ((size_t)bh * HDsz) * Ssz;

    #pragma unroll
    for (int i = 0; i < 4; ++i) {
        int idx = tid + i * 256; int r = idx >> 3, c = idx & 7;
        cpa16(smB + (FQ_OFF + r * FQS) * 2 + c * 16, Qg + (size_t)r * Dsz + c * 8);
    }
    #pragma unroll
    for (int i = 0; i < 4; ++i) {
        int idx = tid + i * 256; int r = idx >> 3, c = idx & 7;
        cpa16(smB + (FK_OFF + r * FQS) * 2 + c * 16, Kg + (size_t)r * Dsz + c * 8);
    }
    #pragma unroll
    for (int i = 0; i < 4; ++i) {
        int idx = tid + i * 256; int n = idx >> 4, c = idx & 15;
        cpa16(smB + (FV_OFF + n * FVS) * 2 + c * 16, Vg + (size_t)n * Ssz + c * 8);
    }
    CPA_COMMIT;

    uint32_t qoff = (uint32_t)((w * 16 + laneRow + ((lt & 1) ? 8 : 0)) * FQS
                               + ((lt & 2) ? 8 : 0));
    uint32_t koff = (uint32_t)((laneRow + ((lt & 2) ? 8 : 0)) * FQS
                               + ((lt & 1) ? 8 : 0));
    uint32_t voff = (uint32_t)((laneRow + ((lt & 2) ? 8 : 0)) * FVS
                               + ((lt & 1) ? 8 : 0));

    float m0 = -1e30f, m1 = -1e30f, l0 = 0.f, l1 = 0.f;
    float ctx[8][4];
    #pragma unroll
    for (int nf = 0; nf < 8; ++nf)
        #pragma unroll
        for (int i = 0; i < 4; ++i) ctx[nf][i] = 0.f;

    int st = 0;
    for (int t = 0; t < 16; ++t) {
        if (t + 1 < 16) {
            int s2 = st ^ 1;
            #pragma unroll
            for (int i = 0; i < 4; ++i) {
                int idx = tid + i * 256; int r = idx >> 3, c = idx & 7;
                cpa16(smB + (FK_OFF + s2 * 9216 + r * FQS) * 2 + c * 16,
                      Kg + ((size_t)((t + 1) * 128 + r)) * Dsz + c * 8);
            }
            #pragma unroll
            for (int i = 0; i < 4; ++i) {
                int idx = tid + i * 256; int n = idx >> 4, c = idx & 15;
                cpa16(smB + (FV_OFF + s2 * 8704 + n * FVS) * 2 + c * 16,
                      Vg + (size_t)n * Ssz + (t + 1) * 128 + c * 8);
            }
            CPA_COMMIT;
            CPA_WAIT(1);
        } else {
            CPA_WAIT(0);
        }
        __syncthreads();

        uint32_t Qsb = smB + FQ_OFF * 2;
        uint32_t Ksb = smB + (FK_OFF + st * 9216) * 2;
        uint32_t Vsb = smB + (FV_OFF + st * 8704) * 2;

        float s4[16][4];
        #pragma unroll
        for (int nf = 0; nf < 16; ++nf)
            #pragma unroll
            for (int i = 0; i < 4; ++i) s4[nf][i] = 0.f;

        #pragma unroll
        for (int kk = 0; kk < 64; kk += 16) {
            uint32_t a[4];
            ldm4(a, Qsb + 2u * (qoff + kk));
            #pragma unroll
            for (int np = 0; np < 8; ++np) {
                uint32_t t4[4];
                ldm4(t4, Ksb + 2u * (koff + (uint32_t)(np * 16 * FQS + kk)));
                mma16816(s4[2*np],     a, t4);
                mma16816(s4[2*np + 1], a, t4 + 2);
            }
        }

        float mx0 = -1e30f, mx1 = -1e30f;
        #pragma unroll
        for (int nf = 0; nf < 16; ++nf) {
            mx0 = fmaxf(mx0, fmaxf(s4[nf][0], s4[nf][1]));
            mx1 = fmaxf(mx1, fmaxf(s4[nf][2], s4[nf][3]));
        }
        mx0 = fmaxf(mx0, __shfl_xor_sync(0xffffffffu, mx0, 1));
        mx0 = fmaxf(mx0, __shfl_xor_sync(0xffffffffu, mx0, 2));
        mx1 = fmaxf(mx1, __shfl_xor_sync(0xffffffffu, mx1, 1));
        mx1 = fmaxf(mx1, __shfl_xor_sync(0xffffffffu, mx1, 2));
        float mn0 = fmaxf(m0, mx0), mn1 = fmaxf(m1, mx1);
        float al0 = __expf(m0 - mn0), al1 = __expf(m1 - mn1);
        float sum0 = 0.f, sum1 = 0.f;
        #pragma unroll
        for (int nf = 0; nf < 16; ++nf) {
            s4[nf][0] = __expf(s4[nf][0] - mn0);
            s4[nf][1] = __expf(s4[nf][1] - mn0);
            s4[nf][2] = __expf(s4[nf][2] - mn1);
            s4[nf][3] = __expf(s4[nf][3] - mn1);
            sum0 += s4[nf][0] + s4[nf][1];
            sum1 += s4[nf][2] + s4[nf][3];
        }
        sum0 += __shfl_xor_sync(0xffffffffu, sum0, 1);
        sum0 += __shfl_xor_sync(0xffffffffu, sum0, 2);
        sum1 += __shfl_xor_sync(0xffffffffu, sum1, 1);
        sum1 += __shfl_xor_sync(0xffffffffu, sum1, 2);
        l0 = l0 * al0 + sum0; l1 = l1 * al1 + sum1;
        m0 = mn0; m1 = mn1;
        #pragma unroll
        for (int nf = 0; nf < 8; ++nf) {
            ctx[nf][0] *= al0; ctx[nf][1] *= al0;
            ctx[nf][2] *= al1; ctx[nf][3] *= al1;
        }

        #pragma unroll
        for (int kc = 0; kc < 8; ++kc) {
            uint32_t a[4];
            a[0] = packbf(s4[2*kc][0],   s4[2*kc][1]);
            a[1] = packbf(s4[2*kc][2],   s4[2*kc][3]);
            a[2] = packbf(s4[2*kc+1][0], s4[2*kc+1][1]);
            a[3] = packbf(s4[2*kc+1][2], s4[2*kc+1][3]);
            #pragma unroll
            for (int np = 0; np < 4; ++np) {
                uint32_t t4[4];
                ldm4(t4, Vsb + 2u * (voff + (uint32_t)(np * 16 * FVS + kc * 16)));
                mma16816(ctx[2*np],     a, t4);
                mma16816(ctx[2*np + 1], a, t4 + 2);
            }
        }

        __syncthreads();
        st ^= 1;
    }

    float i0 = 1.f / l0, i1 = 1.f / l1;
    size_t rbase = (qRow0 + w * 16 + gid) * Dsz + h * HDsz;
    #pragma unroll
    for (int nf = 0; nf < 8; ++nf) {
        int col = nf * 8 + 2 * tig;
        float v00 = ctx[nf][0] * i0, v01 = ctx[nf][1] * i0;
        float v10 = ctx[nf][2] * i1, v11 = ctx[nf][3] * i1;
        __nv_bfloat16 h00 = __float2bfloat16_rn(v00), h01 = __float2bfloat16_rn(v01);
        __nv_bfloat16 h10 = __float2bfloat16_rn(v10), h11 = __float2bfloat16_rn(v11);
        uint32_t uh0 = (uint32_t)__bfloat16_as_ushort(h00) | ((uint32_t)__bfloat16_as_ushort(h01) << 16);
        uint32_t uh1 = (uint32_t)__bfloat16_as_ushort(h10) | ((uint32_t)__bfloat16_as_ushort(h11) << 16);
        uint32_t ul0 = packbf(v00 - __bfloat162float(h00), v01 - __bfloat162float(h01));
        uint32_t ul1 = packbf(v10 - __bfloat162float(h10), v11 - __bfloat162float(h11));
        *reinterpret_cast<uint32_t*>(ctxh + rbase + col) = uh0;
        *reinterpret_cast<uint32_t*>(ctxh + rbase + (size_t)8 * Dsz + col) = uh1;
        *reinterpret_cast<uint32_t*>(ctxl + rbase + col) = ul0;
        *reinterpret_cast<uint32_t*>(ctxl + rbase + (size_t)8 * Dsz + col) = ul1;
    }
}

// ---------------- launch ----------------------------------------------------
extern "C" void kernel_launch(void* const* d_in, const int* in_sizes, int n_in,
                              void* d_out, int out_size)
{
    const float* x    = (const float*)d_in[0];
    const float* fc   = (const float*)d_in[2];
    const float* fs   = (const float*)d_in[3];
    const float* Wq   = (const float*)d_in[4];
    const float* Wk   = (const float*)d_in[5];
    const float* Wv   = (const float*)d_in[6];
    const float* Wo   = (const float*)d_in[7];
    const float* bo   = (const float*)d_in[8];
    const float* ln1g = (const float*)d_in[9];
    const float* ln1b = (const float*)d_in[10];
    const float* ln2g = (const float*)d_in[11];
    const float* ln2b = (const float*)d_in[12];
    const float* W1   = (const float*)d_in[13];
    const float* b1   = (const float*)d_in[14];
    const float* W2   = (const float*)d_in[15];
    const float* b2   = (const float*)d_in[16];
    float* out = (float*)d_out;

    float *x1;
    cudaGetSymbolAddress((void**)&x1, g_x1);

    __nv_bfloat16 *xnh,*xnl,*xn2h,*xn2l,*ctxh,*ctxl,*hh,*hl,*qb,*kb,*vt;
    cudaGetSymbolAddress((void**)&xnh,  g_xnh);  cudaGetSymbolAddress((void**)&xnl,  g_xnl);
    cudaGetSymbolAddress((void**)&xn2h, g_xn2h); cudaGetSymbolAddress((void**)&xn2l, g_xn2l);
    cudaGetSymbolAddress((void**)&ctxh, g_ctxh); cudaGetSymbolAddress((void**)&ctxl, g_ctxl);
    cudaGetSymbolAddress((void**)&hh,   g_hh);   cudaGetSymbolAddress((void**)&hl,   g_hl);
    cudaGetSymbolAddress((void**)&qb,   g_qb);
    cudaGetSymbolAddress((void**)&kb,   g_kb);
    cudaGetSymbolAddress((void**)&vt,   g_vt);

    __nv_bfloat16 *wqkvh,*wqkvl,*woh,*wol,*w1h,*w1l,*w2h,*w2l;
    cudaGetSymbolAddress((void**)&wqkvh, g_wqkv_h); cudaGetSymbolAddress((void**)&wqkvl, g_wqkv_l);
    cudaGetSymbolAddress((void**)&woh, g_wo_h); cudaGetSymbolAddress((void**)&wol, g_wo_l);
    cudaGetSymbolAddress((void**)&w1h, g_w1_h); cudaGetSymbolAddress((void**)&w1l, g_w1_l);
    cudaGetSymbolAddress((void**)&w2h, g_w2_h); cudaGetSymbolAddress((void**)&w2l, g_w2_l);

    cudaFuncSetAttribute(bgemm, cudaFuncAttributeMaxDynamicSharedMemorySize, BG_SMEM);
    cudaFuncSetAttribute(flash_kernel, cudaFuncAttributeMaxDynamicSharedMemorySize, FSM_BYTES);

    // 0. all weight conversions in one launch
    wconv_all_kernel<<<12288, 256>>>(Wq, Wk, Wv, Wo, W1, W2,
                                     wqkvh, wqkvl, woh, wol, w1h, w1l, w2h, w2l);

    // 1. LN1 -> bf16 hi/lo
    ln_bf_kernel<<<ROWS, 256>>>(x, ln1g, ln1b, xnh, xnl);

    // 2. fused QKV projection with rope/vt epilogue (act=2), 256x128 tiles
    dim3 gQKV(3*Dsz/128, ROWS/256);
    bgemm<<<gQKV, 512, BG_SMEM>>>(xnh, xnl, wqkvh, wqkvl, nullptr, nullptr, nullptr,
                                  Dsz, 3*Dsz, nullptr, nullptr, 2, fc, fs, qb, kb, vt);

    // 3-6. flash attention -> ctx hi/lo
    flash_kernel<<<dim3(Ssz/128, Bsz*Hsz), 256, FSM_BYTES>>>(qb, kb, vt, ctxh, ctxl);

    // 7. x1 = x + ctx @ Wo + bo
    dim3 gQ(Dsz / 128, ROWS / 256);
    bgemm<<<gQ, 512, BG_SMEM>>>(ctxh, ctxl, woh, wol, x1, nullptr, nullptr,
                                Dsz, Dsz, bo, x, 0, nullptr, nullptr, nullptr, nullptr, nullptr);

    // 8. LN2 -> bf16 hi/lo
    ln_bf_kernel<<<ROWS, 256>>>(x1, ln2g, ln2b, xn2h, xn2l);

    // 9. h = gelu(xn2 @ W1 + b1) -> bf16 hi/lo
    dim3 gF1(DFFsz / 128, ROWS / 256);
    bgemm<<<gF1, 512, BG_SMEM>>>(xn2h, xn2l, w1h, w1l, nullptr, hh, hl,
                                 Dsz, DFFsz, b1, nullptr, 1, nullptr, nullptr, nullptr, nullptr, nullptr);

    // 10. out = x1 + h @ W2 + b2
    bgemm<<<gQ, 512, BG_SMEM>>>(hh, hl, w2h, w2l, out, nullptr, nullptr,
                                DFFsz, Dsz, b2, x1, 0, nullptr, nullptr, nullptr, nullptr, nullptr);
}

// round 14
// speedup vs baseline: 1.0960x; 1.0960x over previous
#include <cuda_runtime.h>
#include <cuda_bf16.h>
#include <math.h>
#include <stdint.h>

// Problem constants
#define Bsz   2
#define Ssz   2048
#define Dsz   1024
#define Hsz   16
#define HDsz  64
#define DFFsz 4096
#define ROWS  (Bsz*Ssz)
#define EPSLN 1e-5f
#define QSCL  0.18033688011112042f   // 0.125 * log2(e): softmax done in exp2 domain

// ---------------- scratch (device globals) ---------------------------------
__device__ float g_x1 [ROWS*Dsz];

__device__ __nv_bfloat16 g_xnh [ROWS*Dsz],  g_xnl [ROWS*Dsz];
__device__ __nv_bfloat16 g_xn2h[ROWS*Dsz],  g_xn2l[ROWS*Dsz];
__device__ __nv_bfloat16 g_ctxh[ROWS*Dsz],  g_ctxl[ROWS*Dsz];
__device__ __nv_bfloat16 g_hh  [ROWS*DFFsz], g_hl [ROWS*DFFsz];

__device__ __nv_bfloat16 g_qb[ROWS*Dsz];
__device__ __nv_bfloat16 g_kb[ROWS*Dsz];
__device__ __nv_bfloat16 g_vt[Bsz*Hsz*HDsz*Ssz];

__device__ __nv_bfloat16 g_wqkv_h[3*Dsz*Dsz], g_wqkv_l[3*Dsz*Dsz];
__device__ __nv_bfloat16 g_wo_h[Dsz*Dsz],  g_wo_l[Dsz*Dsz];
__device__ __nv_bfloat16 g_w1_h[Dsz*DFFsz], g_w1_l[Dsz*DFFsz];
__device__ __nv_bfloat16 g_w2_h[DFFsz*Dsz], g_w2_l[DFFsz*Dsz];

// ---------------- helpers ---------------------------------------------------
__device__ __forceinline__ uint32_t smem_u32(const void* p) {
    uint32_t a;
    asm("{ .reg .u64 t; cvta.to.shared.u64 t, %1; cvt.u32.u64 %0, t; }"
        : "=r"(a) : "l"(p));
    return a;
}
__device__ __forceinline__ void cpa16(uint32_t d, const void* s) {
    asm volatile("cp.async.cg.shared.global [%0], [%1], 16;" :: "r"(d), "l"(s));
}
#define CPA_COMMIT asm volatile("cp.async.commit_group;" ::: "memory")
#define CPA_WAIT(n) asm volatile("cp.async.wait_group %0;" :: "n"(n) : "memory")

__device__ __forceinline__ void ldm4(uint32_t* d, uint32_t a) {
    asm volatile("ldmatrix.sync.aligned.m8n8.x4.shared.b16 {%0,%1,%2,%3}, [%4];"
        : "=r"(d[0]), "=r"(d[1]), "=r"(d[2]), "=r"(d[3]) : "r"(a));
}
__device__ __forceinline__ float gelu_exact(float x) {
    return 0.5f * x * (1.0f + erff(x * 0.70710678118654752440f));
}
__device__ __forceinline__ uint32_t packbf(float x, float y) {
    uint32_t lo = __bfloat16_as_ushort(__float2bfloat16_rn(x));
    uint32_t hi = __bfloat16_as_ushort(__float2bfloat16_rn(y));
    return lo | (hi << 16);
}
__device__ __forceinline__ void mma16816(float* c, const uint32_t* a, const uint32_t* b) {
    asm volatile(
        "mma.sync.aligned.m16n8k16.row.col.f32.bf16.bf16.f32 "
        "{%0,%1,%2,%3}, {%4,%5,%6,%7}, {%8,%9}, {%0,%1,%2,%3};"
        : "+f"(c[0]), "+f"(c[1]), "+f"(c[2]), "+f"(c[3])
        : "r"(a[0]), "r"(a[1]), "r"(a[2]), "r"(a[3]), "r"(b[0]), "r"(b[1]));
}

__device__ __forceinline__ float block_sum(float v) {
    __shared__ float sh[8];
    int lane = threadIdx.x & 31, w = threadIdx.x >> 5;
    #pragma unroll
    for (int o = 16; o > 0; o >>= 1) v += __shfl_down_sync(0xffffffffu, v, o);
    if (!lane) sh[w] = v;
    __syncthreads();
    if (w == 0) {
        float t = (lane < 8) ? sh[lane] : 0.f;
        #pragma unroll
        for (int o = 4; o > 0; o >>= 1) t += __shfl_down_sync(0xffu, t, o);
        if (lane == 0) sh[0] = t;
    }
    __syncthreads();
    float r = sh[0];
    __syncthreads();
    return r;
}

// ---------------- layernorm -> bf16 hi/lo ----------------------------------
__global__ __launch_bounds__(256) void ln_bf_kernel(
    const float* __restrict__ x, const float* __restrict__ g,
    const float* __restrict__ b,
    __nv_bfloat16* __restrict__ oh, __nv_bfloat16* __restrict__ ol)
{
    int row = blockIdx.x, tid = threadIdx.x;
    const float* xr = x + (long long)row * Dsz;
    float4 v = *reinterpret_cast<const float4*>(xr + tid * 4);
    float mu = block_sum(v.x + v.y + v.z + v.w) * (1.0f / Dsz);
    float d0 = v.x - mu, d1 = v.y - mu, d2 = v.z - mu, d3 = v.w - mu;
    float var = block_sum(d0*d0 + d1*d1 + d2*d2 + d3*d3) * (1.0f / Dsz);
    float inv = rsqrtf(var + EPSLN);
    float4 gg = *reinterpret_cast<const float4*>(g + tid * 4);
    float4 bb = *reinterpret_cast<const float4*>(b + tid * 4);
    float o0 = d0 * inv * gg.x + bb.x;
    float o1 = d1 * inv * gg.y + bb.y;
    float o2 = d2 * inv * gg.z + bb.z;
    float o3 = d3 * inv * gg.w + bb.w;
    __nv_bfloat16 h0 = __float2bfloat16_rn(o0), h1 = __float2bfloat16_rn(o1);
    __nv_bfloat16 h2 = __float2bfloat16_rn(o2), h3 = __float2bfloat16_rn(o3);
    uint2 uh, ul;
    uh.x = (uint32_t)__bfloat16_as_ushort(h0) | ((uint32_t)__bfloat16_as_ushort(h1) << 16);
    uh.y = (uint32_t)__bfloat16_as_ushort(h2) | ((uint32_t)__bfloat16_as_ushort(h3) << 16);
    ul.x = packbf(o0 - __bfloat162float(h0), o1 - __bfloat162float(h1));
    ul.y = packbf(o2 - __bfloat162float(h2), o3 - __bfloat162float(h3));
    long long off = (long long)row * Dsz + tid * 4;
    *reinterpret_cast<uint2*>(oh + off) = uh;
    *reinterpret_cast<uint2*>(ol + off) = ul;
}

// ---------------- merged weight transpose + bf16 hi/lo split ---------------
__global__ __launch_bounds__(256) void wconv_all_kernel(
    const float* __restrict__ Wq, const float* __restrict__ Wk,
    const float* __restrict__ Wv, const float* __restrict__ Wo,
    const float* __restrict__ W1, const float* __restrict__ W2,
    __nv_bfloat16* __restrict__ wqkvh, __nv_bfloat16* __restrict__ wqkvl,
    __nv_bfloat16* __restrict__ woh,   __nv_bfloat16* __restrict__ wol,
    __nv_bfloat16* __restrict__ w1h,   __nv_bfloat16* __restrict__ w1l,
    __nv_bfloat16* __restrict__ w2h,   __nv_bfloat16* __restrict__ w2l)
{
    int idx = blockIdx.x;
    const float* W; __nv_bfloat16 *Th, *Tl; int K, N, seg;
    if (idx < 4096) {
        K = Dsz; N = Dsz; seg = idx & 1023;
        int which = idx >> 10;
        if (which == 0) { W = Wq; Th = wqkvh;             Tl = wqkvl; }
        else if (which == 1) { W = Wk; Th = wqkvh + Dsz*Dsz;   Tl = wqkvl + Dsz*Dsz; }
        else if (which == 2) { W = Wv; Th = wqkvh + 2*Dsz*Dsz; Tl = wqkvl + 2*Dsz*Dsz; }
        else { W = Wo; Th = woh; Tl = wol; }
    } else if (idx < 8192) {
        K = Dsz; N = DFFsz; seg = idx - 4096; W = W1; Th = w1h; Tl = w1l;
    } else {
        K = DFFsz; N = Dsz; seg = idx - 8192; W = W2; Th = w2h; Tl = w2l;
    }
    int nBN = N / 32;
    int n0 = (seg % nBN) * 32, k0 = (seg / nBN) * 32;

    __shared__ float t[32][33];
    int tx = threadIdx.x & 31, ty = threadIdx.x >> 5;
    #pragma unroll
    for (int r = 0; r < 4; ++r)
        t[ty + r * 8][tx] = W[(size_t)(k0 + ty + r * 8) * N + n0 + tx];
    __syncthreads();
    #pragma unroll
    for (int r = 0; r < 4; ++r) {
        int n = n0 + ty + r * 8, k = k0 + tx;
        float w = t[tx][ty + r * 8];
        __nv_bfloat16 hi = __float2bfloat16_rn(w);
        __nv_bfloat16 lo = __float2bfloat16_rn(w - __bfloat162float(hi));
        Th[(size_t)n * K + k] = hi;
        Tl[(size_t)n * K + k] = lo;
    }
}

// ---------------- bf16x3 GEMM: cp.async + ldmatrix, 2 CTAs/SM (R11 cfg) ----
// act: 0 = plain, 1 = gelu, 2 = fused QKV epilogue (rope->qb/kb, transpose->vt)
#define PADK     40
#define AH_OFF   0
#define AL_OFF   5120
#define BH_OFF   10240
#define BL_OFF   15360
#define SSTRIDE  20480
#define BG_SMEM  (2 * SSTRIDE * 2)

__global__ __launch_bounds__(256, 2) void bgemm(
    const __nv_bfloat16* __restrict__ Ah, const __nv_bfloat16* __restrict__ Al,
    const __nv_bfloat16* __restrict__ Bh, const __nv_bfloat16* __restrict__ Bl,
    float* __restrict__ C,
    __nv_bfloat16* __restrict__ Oh, __nv_bfloat16* __restrict__ Ol,
    int K, int N,
    const float* __restrict__ bias, const float* __restrict__ resid, int act,
    const float* __restrict__ fc, const float* __restrict__ fs,
    __nv_bfloat16* __restrict__ qb, __nv_bfloat16* __restrict__ kb,
    __nv_bfloat16* __restrict__ vt)
{
    extern __shared__ unsigned short sm[];
    uint32_t smB = smem_u32(sm);
    int tid = threadIdx.x, lane = tid & 31, wid = tid >> 5;
    int wr = wid >> 2, wc = wid & 3;
    int gid = lane >> 2, tig = lane & 3;
    int laneRow = lane & 7, lt = lane >> 3;
    int tileN = blockIdx.x * 128, tileM = blockIdx.y * 128;

    const __nv_bfloat16* Ahb = Ah + (size_t)tileM * K;
    const __nv_bfloat16* Alb = Al + (size_t)tileM * K;
    const __nv_bfloat16* Bhb = Bh + (size_t)tileN * K;
    const __nv_bfloat16* Blb = Bl + (size_t)tileN * K;

    float acc[4][4][4];
    #pragma unroll
    for (int mf = 0; mf < 4; ++mf)
        #pragma unroll
        for (int nf = 0; nf < 4; ++nf)
            #pragma unroll
            for (int i = 0; i < 4; ++i) acc[mf][nf][i] = 0.f;

    uint32_t aoff = (uint32_t)((wr * 64 + laneRow + ((lt & 1) ? 8 : 0)) * PADK
                               + ((lt & 2) ? 8 : 0));
    uint32_t boff = (uint32_t)((wc * 32 + laneRow + ((lt & 2) ? 8 : 0)) * PADK
                               + ((lt & 1) ? 8 : 0));

    int row0 = tid >> 2, c4 = tid & 3;
    int row1 = row0 + 64;

    int nCh = K >> 5;

    {
        uint32_t sb = smB;
        uint32_t d0 = (uint32_t)(row0 * PADK + c4 * 8) * 2;
        uint32_t d1 = (uint32_t)(row1 * PADK + c4 * 8) * 2;
        size_t s0 = (size_t)row0 * K + c4 * 8;
        size_t s1 = (size_t)row1 * K + c4 * 8;
        cpa16(sb + AH_OFF*2 + d0, Ahb + s0); cpa16(sb + AH_OFF*2 + d1, Ahb + s1);
        cpa16(sb + AL_OFF*2 + d0, Alb + s0); cpa16(sb + AL_OFF*2 + d1, Alb + s1);
        cpa16(sb + BH_OFF*2 + d0, Bhb + s0); cpa16(sb + BH_OFF*2 + d1, Bhb + s1);
        cpa16(sb + BL_OFF*2 + d0, Blb + s0); cpa16(sb + BL_OFF*2 + d1, Blb + s1);
        CPA_COMMIT;
    }

    for (int c = 0; c < nCh; ++c) {
        int s = c & 1;
        if (c + 1 < nCh) {
            int k0 = (c + 1) << 5;
            uint32_t sb = smB + (uint32_t)(s ^ 1) * (SSTRIDE * 2);
            uint32_t d0 = (uint32_t)(row0 * PADK + c4 * 8) * 2;
            uint32_t d1 = (uint32_t)(row1 * PADK + c4 * 8) * 2;
            size_t s0 = (size_t)row0 * K + k0 + c4 * 8;
            size_t s1 = (size_t)row1 * K + k0 + c4 * 8;
            cpa16(sb + AH_OFF*2 + d0, Ahb + s0); cpa16(sb + AH_OFF*2 + d1, Ahb + s1);
            cpa16(sb + AL_OFF*2 + d0, Alb + s0); cpa16(sb + AL_OFF*2 + d1, Alb + s1);
            cpa16(sb + BH_OFF*2 + d0, Bhb + s0); cpa16(sb + BH_OFF*2 + d1, Bhb + s1);
            cpa16(sb + BL_OFF*2 + d0, Blb + s0); cpa16(sb + BL_OFF*2 + d1, Blb + s1);
            CPA_COMMIT;
            CPA_WAIT(1);
        } else {
            CPA_WAIT(0);
        }
        __syncthreads();

        uint32_t stb = smB + (uint32_t)s * (SSTRIDE * 2);
        #pragma unroll
        for (int kk = 0; kk < 32; kk += 16) {
            uint32_t ah[4][4], al[4][4], bh[4][2], bl[4][2];
            #pragma unroll
            for (int mf = 0; mf < 4; ++mf) {
                uint32_t ad = stb + 2u * (aoff + (uint32_t)(mf * 16 * PADK + kk));
                ldm4(ah[mf], ad + 2u * AH_OFF);
                ldm4(al[mf], ad + 2u * AL_OFF);
            }
            #pragma unroll
            for (int np = 0; np < 2; ++np) {
                uint32_t bd = stb + 2u * (boff + (uint32_t)(np * 16 * PADK + kk));
                uint32_t t4[4];
                ldm4(t4, bd + 2u * BH_OFF);
                bh[2*np][0] = t4[0]; bh[2*np][1] = t4[1];
                bh[2*np+1][0] = t4[2]; bh[2*np+1][1] = t4[3];
                ldm4(t4, bd + 2u * BL_OFF);
                bl[2*np][0] = t4[0]; bl[2*np][1] = t4[1];
                bl[2*np+1][0] = t4[2]; bl[2*np+1][1] = t4[3];
            }
            #pragma unroll
            for (int mf = 0; mf < 4; ++mf)
                #pragma unroll
                for (int nf = 0; nf < 4; ++nf) {
                    mma16816(acc[mf][nf], ah[mf], bh[nf]);
                    mma16816(acc[mf][nf], ah[mf], bl[nf]);
                    mma16816(acc[mf][nf], al[mf], bh[nf]);
                }
        }
        __syncthreads();
    }

    // ---- epilogue ----
    if (act == 2) {
        // fused QKV: rope -> qb/kb (Q scaled to exp2 domain), transpose -> vt.
        #pragma unroll
        for (int mf = 0; mf < 4; ++mf) {
            int row = tileM + wr * 64 + mf * 16 + gid;
            #pragma unroll
            for (int nf = 0; nf < 4; ++nf) {
                int col = tileN + wc * 32 + nf * 8 + 2 * tig;
                #pragma unroll
                for (int half = 0; half < 2; ++half) {
                    int r = row + half * 8;
                    float e = acc[mf][nf][2*half];
                    float o = acc[mf][nf][2*half + 1];
                    int srow = r & (Ssz - 1);
                    if (col < Dsz) {
                        int i = (col & 63) >> 1;
                        float cv = fc[srow * 32 + i], sv = fs[srow * 32 + i];
                        float r0 = (e * cv - o * sv) * QSCL;
                        float r1 = (e * sv + o * cv) * QSCL;
                        __nv_bfloat162 p;
                        p.x = __float2bfloat16_rn(r0); p.y = __float2bfloat16_rn(r1);
                        *reinterpret_cast<__nv_bfloat162*>(qb + (size_t)r * Dsz + col) = p;
                    } else if (col < 2 * Dsz) {
                        int cc = col - Dsz;
                        int i = (cc & 63) >> 1;
                        float cv = fc[srow * 32 + i], sv = fs[srow * 32 + i];
                        float r0 = e * cv - o * sv;
                        float r1 = e * sv + o * cv;
                        __nv_bfloat162 p;
                        p.x = __float2bfloat16_rn(r0); p.y = __float2bfloat16_rn(r1);
                        *reinterpret_cast<__nv_bfloat162*>(kb + (size_t)r * Dsz + cc) = p;
                    } else {
                        int cc = col - 2 * Dsz;
                        int h = cc >> 6, n = cc & 63;
                        int bh = (r >> 11) * Hsz + h;
                        size_t base = ((size_t)bh * HDsz) * Ssz + srow;
                        vt[base + (size_t)n * Ssz]       = __float2bfloat16_rn(e);
                        vt[base + (size_t)(n + 1) * Ssz] = __float2bfloat16_rn(o);
                    }
                }
            }
        }
        return;
    }

    #pragma unroll
    for (int mf = 0; mf < 4; ++mf) {
        int row = tileM + wr * 64 + mf * 16 + gid;
        #pragma unroll
        for (int nf = 0; nf < 4; ++nf) {
            int col = tileN + wc * 32 + nf * 8 + 2 * tig;
            float2 v0 = make_float2(acc[mf][nf][0], acc[mf][nf][1]);
            float2 v1 = make_float2(acc[mf][nf][2], acc[mf][nf][3]);
            if (bias) {
                float2 bv = *reinterpret_cast<const float2*>(bias + col);
                v0.x += bv.x; v0.y += bv.y;
                v1.x += bv.x; v1.y += bv.y;
            }
            if (act == 1) {
                v0.x = gelu_exact(v0.x); v0.y = gelu_exact(v0.y);
                v1.x = gelu_exact(v1.x); v1.y = gelu_exact(v1.y);
            }
            size_t i0 = (size_t)row * N + col;
            size_t i1 = (size_t)(row + 8) * N + col;
            if (resid) {
                float2 r0 = *reinterpret_cast<const float2*>(resid + i0);
                float2 r1 = *reinterpret_cast<const float2*>(resid + i1);
                v0.x += r0.x; v0.y += r0.y;
                v1.x += r1.x; v1.y += r1.y;
            }
            if (C) {
                *reinterpret_cast<float2*>(C + i0) = v0;
                *reinterpret_cast<float2*>(C + i1) = v1;
            }
            if (Oh) {
                __nv_bfloat16 h0 = __float2bfloat16_rn(v0.x), h1 = __float2bfloat16_rn(v0.y);
                __nv_bfloat16 h2 = __float2bfloat16_rn(v1.x), h3 = __float2bfloat16_rn(v1.y);
                uint32_t uh0 = (uint32_t)__bfloat16_as_ushort(h0) | ((uint32_t)__bfloat16_as_ushort(h1) << 16);
                uint32_t uh1 = (uint32_t)__bfloat16_as_ushort(h2) | ((uint32_t)__bfloat16_as_ushort(h3) << 16);
                uint32_t ul0 = packbf(v0.x - __bfloat162float(h0), v0.y - __bfloat162float(h1));
                uint32_t ul1 = packbf(v1.x - __bfloat162float(h2), v1.y - __bfloat162float(h3));
                *reinterpret_cast<uint32_t*>(Oh + i0) = uh0;
                *reinterpret_cast<uint32_t*>(Oh + i1) = uh1;
                *reinterpret_cast<uint32_t*>(Ol + i0) = ul0;
                *reinterpret_cast<uint32_t*>(Ol + i1) = ul1;
            }
        }
    }
}

// ---------------- fused flash attention (2 CTAs/SM, exp2 softmax) ----------
#define FQS 72
#define FVS 136
#define FQ_OFF 0
#define FK_OFF 9216
#define FV_OFF (9216 + 2*9216)
#define FSM_BYTES ((FV_OFF + 2*8704) * 2)

__global__ __launch_bounds__(256, 2) void flash_kernel(
    const __nv_bfloat16* __restrict__ Qb, const __nv_bfloat16* __restrict__ Kb,
    const __nv_bfloat16* __restrict__ Vt,
    __nv_bfloat16* __restrict__ ctxh, __nv_bfloat16* __restrict__ ctxl)
{
    extern __shared__ unsigned short fsm[];
    uint32_t smB = smem_u32(fsm);
    int tid = threadIdx.x, lane = tid & 31, w = tid >> 5;
    int gid = lane >> 2, tig = lane & 3;
    int laneRow = lane & 7, lt = lane >> 3;
    int tq = blockIdx.x, bh = blockIdx.y;
    int b = bh >> 4, h = bh & 15;

    size_t qRow0 = (size_t)b * Ssz + tq * 128;
    const __nv_bfloat16* Qg = Qb + qRow0 * Dsz + h * HDsz;
    const __nv_bfloat16* Kg = Kb + ((size_t)b * Ssz) * Dsz + h * HDsz;
    const __nv_bfloat16* Vg = Vt + ((size_t)bh * HDsz) * Ssz;

    #pragma unroll
    for (int i = 0; i < 4; ++i) {
        int idx = tid + i * 256; int r = idx >> 3, c = idx & 7;
        cpa16(smB + (FQ_OFF + r * FQS) * 2 + c * 16, Qg + (size_t)r * Dsz + c * 8);
    }
    #pragma unroll
    for (int i = 0; i < 4; ++i) {
        int idx = tid + i * 256; int r = idx >> 3, c = idx & 7;
        cpa16(smB + (FK_OFF + r * FQS) * 2 + c * 16, Kg + (size_t)r * Dsz + c * 8);
    }
    #pragma unroll
    for (int i = 0; i < 4; ++i) {
        int idx = tid + i * 256; int n = idx >> 4, c = idx & 15;
        cpa16(smB + (FV_OFF + n * FVS) * 2 + c * 16, Vg + (size_t)n * Ssz + c * 8);
    }
    CPA_COMMIT;

    uint32_t qoff = (uint32_t)((w * 16 + laneRow + ((lt & 1) ? 8 : 0)) * FQS
                               + ((lt & 2) ? 8 : 0));
    uint32_t koff = (uint32_t)((laneRow + ((lt & 2) ? 8 : 0)) * FQS
                               + ((lt & 1) ? 8 : 0));
    uint32_t voff = (uint32_t)((laneRow + ((lt & 2) ? 8 : 0)) * FVS
                               + ((lt & 1) ? 8 : 0));

    float m0 = -1e30f, m1 = -1e30f, l0 = 0.f, l1 = 0.f;
    float ctx[8][4];
    #pragma unroll
    for (int nf = 0; nf < 8; ++nf)
        #pragma unroll
        for (int i = 0; i < 4; ++i) ctx[nf][i] = 0.f;

    int st = 0;
    for (int t = 0; t < 16; ++t) {
        if (t + 1 < 16) {
            int s2 = st ^ 1;
            #pragma unroll
            for (int i = 0; i < 4; ++i) {
                int idx = tid + i * 256; int r = idx >> 3, c = idx & 7;
                cpa16(smB + (FK_OFF + s2 * 9216 + r * FQS) * 2 + c * 16,
                      Kg + ((size_t)((t + 1) * 128 + r)) * Dsz + c * 8);
            }
            #pragma unroll
            for (int i = 0; i < 4; ++i) {
                int idx = tid + i * 256; int n = idx >> 4, c = idx & 15;
                cpa16(smB + (FV_OFF + s2 * 8704 + n * FVS) * 2 + c * 16,
                      Vg + (size_t)n * Ssz + (t + 1) * 128 + c * 8);
            }
            CPA_COMMIT;
            CPA_WAIT(1);
        } else {
            CPA_WAIT(0);
        }
        __syncthreads();

        uint32_t Qsb = smB + FQ_OFF * 2;
        uint32_t Ksb = smB + (FK_OFF + st * 9216) * 2;
        uint32_t Vsb = smB + (FV_OFF + st * 8704) * 2;

        // ---- S = Q K^T (scores already in log2 domain via QSCL) ----
        float s4[16][4];
        #pragma unroll
        for (int nf = 0; nf < 16; ++nf)
            #pragma unroll
            for (int i = 0; i < 4; ++i) s4[nf][i] = 0.f;

        #pragma unroll
        for (int kk = 0; kk < 64; kk += 16) {
            uint32_t a[4];
            ldm4(a, Qsb + 2u * (qoff + kk));
            #pragma unroll
            for (int np = 0; np < 8; ++np) {
                uint32_t t4[4];
                ldm4(t4, Ksb + 2u * (koff + (uint32_t)(np * 16 * FQS + kk)));
                mma16816(s4[2*np],     a, t4);
                mma16816(s4[2*np + 1], a, t4 + 2);
            }
        }

        // ---- online softmax (exp2 domain) ----
        float mx0 = -1e30f, mx1 = -1e30f;
        #pragma unroll
        for (int nf = 0; nf < 16; ++nf) {
            mx0 = fmaxf(mx0, fmaxf(s4[nf][0], s4[nf][1]));
            mx1 = fmaxf(mx1, fmaxf(s4[nf][2], s4[nf][3]));
        }
        mx0 = fmaxf(mx0, __shfl_xor_sync(0xffffffffu, mx0, 1));
        mx0 = fmaxf(mx0, __shfl_xor_sync(0xffffffffu, mx0, 2));
        mx1 = fmaxf(mx1, __shfl_xor_sync(0xffffffffu, mx1, 1));
        mx1 = fmaxf(mx1, __shfl_xor_sync(0xffffffffu, mx1, 2));
        float mn0 = fmaxf(m0, mx0), mn1 = fmaxf(m1, mx1);
        float al0 = exp2f(m0 - mn0), al1 = exp2f(m1 - mn1);
        float sum0 = 0.f, sum1 = 0.f;
        #pragma unroll
        for (int nf = 0; nf < 16; ++nf) {
            s4[nf][0] = exp2f(s4[nf][0] - mn0);
            s4[nf][1] = exp2f(s4[nf][1] - mn0);
            s4[nf][2] = exp2f(s4[nf][2] - mn1);
            s4[nf][3] = exp2f(s4[nf][3] - mn1);
            sum0 += s4[nf][0] + s4[nf][1];
            sum1 += s4[nf][2] + s4[nf][3];
        }
        sum0 += __shfl_xor_sync(0xffffffffu, sum0, 1);
        sum0 += __shfl_xor_sync(0xffffffffu, sum0, 2);
        sum1 += __shfl_xor_sync(0xffffffffu, sum1, 1);
        sum1 += __shfl_xor_sync(0xffffffffu, sum1, 2);
        l0 = l0 * al0 + sum0; l1 = l1 * al1 + sum1;
        m0 = mn0; m1 = mn1;
        #pragma unroll
        for (int nf = 0; nf < 8; ++nf) {
            ctx[nf][0] *= al0; ctx[nf][1] *= al0;
            ctx[nf][2] *= al1; ctx[nf][3] *= al1;
        }

        // ---- ctx += P @ V ----
        #pragma unroll
        for (int kc = 0; kc < 8; ++kc) {
            uint32_t a[4];
            a[0] = packbf(s4[2*kc][0],   s4[2*kc][1]);
            a[1] = packbf(s4[2*kc][2],   s4[2*kc][3]);
            a[2] = packbf(s4[2*kc+1][0], s4[2*kc+1][1]);
            a[3] = packbf(s4[2*kc+1][2], s4[2*kc+1][3]);
            #pragma unroll
            for (int np = 0; np < 4; ++np) {
                uint32_t t4[4];
                ldm4(t4, Vsb + 2u * (voff + (uint32_t)(np * 16 * FVS + kc * 16)));
                mma16816(ctx[2*np],     a, t4);
                mma16816(ctx[2*np + 1], a, t4 + 2);
            }
        }

        __syncthreads();
        st ^= 1;
    }

    float i0 = 1.f / l0, i1 = 1.f / l1;
    size_t rbase = (qRow0 + w * 16 + gid) * Dsz + h * HDsz;
    #pragma unroll
    for (int nf = 0; nf < 8; ++nf) {
        int col = nf * 8 + 2 * tig;
        float v00 = ctx[nf][0] * i0, v01 = ctx[nf][1] * i0;
        float v10 = ctx[nf][2] * i1, v11 = ctx[nf][3] * i1;
        __nv_bfloat16 h00 = __float2bfloat16_rn(v00), h01 = __float2bfloat16_rn(v01);
        __nv_bfloat16 h10 = __float2bfloat16_rn(v10), h11 = __float2bfloat16_rn(v11);
        uint32_t uh0 = (uint32_t)__bfloat16_as_ushort(h00) | ((uint32_t)__bfloat16_as_ushort(h01) << 16);
        uint32_t uh1 = (uint32_t)__bfloat16_as_ushort(h10) | ((uint32_t)__bfloat16_as_ushort(h11) << 16);
        uint32_t ul0 = packbf(v00 - __bfloat162float(h00), v01 - __bfloat162float(h01));
        uint32_t ul1 = packbf(v10 - __bfloat162float(h10), v11 - __bfloat162float(h11));
        *reinterpret_cast<uint32_t*>(ctxh + rbase + col) = uh0;
        *reinterpret_cast<uint32_t*>(ctxh + rbase + (size_t)8 * Dsz + col) = uh1;
        *reinterpret_cast<uint32_t*>(ctxl + rbase + col) = ul0;
        *reinterpret_cast<uint32_t*>(ctxl + rbase + (size_t)8 * Dsz + col) = ul1;
    }
}

// ---------------- launch ----------------------------------------------------
extern "C" void kernel_launch(void* const* d_in, const int* in_sizes, int n_in,
                              void* d_out, int out_size)
{
    const float* x    = (const float*)d_in[0];
    const float* fc   = (const float*)d_in[2];
    const float* fs   = (const float*)d_in[3];
    const float* Wq   = (const float*)d_in[4];
    const float* Wk   = (const float*)d_in[5];
    const float* Wv   = (const float*)d_in[6];
    const float* Wo   = (const float*)d_in[7];
    const float* bo   = (const float*)d_in[8];
    const float* ln1g = (const float*)d_in[9];
    const float* ln1b = (const float*)d_in[10];
    const float* ln2g = (const float*)d_in[11];
    const float* ln2b = (const float*)d_in[12];
    const float* W1   = (const float*)d_in[13];
    const float* b1   = (const float*)d_in[14];
    const float* W2   = (const float*)d_in[15];
    const float* b2   = (const float*)d_in[16];
    float* out = (float*)d_out;

    float *x1;
    cudaGetSymbolAddress((void**)&x1, g_x1);

    __nv_bfloat16 *xnh,*xnl,*xn2h,*xn2l,*ctxh,*ctxl,*hh,*hl,*qb,*kb,*vt;
    cudaGetSymbolAddress((void**)&xnh,  g_xnh);  cudaGetSymbolAddress((void**)&xnl,  g_xnl);
    cudaGetSymbolAddress((void**)&xn2h, g_xn2h); cudaGetSymbolAddress((void**)&xn2l, g_xn2l);
    cudaGetSymbolAddress((void**)&ctxh, g_ctxh); cudaGetSymbolAddress((void**)&ctxl, g_ctxl);
    cudaGetSymbolAddress((void**)&hh,   g_hh);   cudaGetSymbolAddress((void**)&hl,   g_hl);
    cudaGetSymbolAddress((void**)&qb,   g_qb);
    cudaGetSymbolAddress((void**)&kb,   g_kb);
    cudaGetSymbolAddress((void**)&vt,   g_vt);

    __nv_bfloat16 *wqkvh,*wqkvl,*woh,*wol,*w1h,*w1l,*w2h,*w2l;
    cudaGetSymbolAddress((void**)&wqkvh, g_wqkv_h); cudaGetSymbolAddress((void**)&wqkvl, g_wqkv_l);
    cudaGetSymbolAddress((void**)&woh, g_wo_h); cudaGetSymbolAddress((void**)&wol, g_wo_l);
    cudaGetSymbolAddress((void**)&w1h, g_w1_h); cudaGetSymbolAddress((void**)&w1l, g_w1_l);
    cudaGetSymbolAddress((void**)&w2h, g_w2_h); cudaGetSymbolAddress((void**)&w2l, g_w2_l);

    cudaFuncSetAttribute(bgemm, cudaFuncAttributeMaxDynamicSharedMemorySize, BG_SMEM);
    cudaFuncSetAttribute(flash_kernel, cudaFuncAttributeMaxDynamicSharedMemorySize, FSM_BYTES);

    // 0. all weight conversions in one launch
    wconv_all_kernel<<<12288, 256>>>(Wq, Wk, Wv, Wo, W1, W2,
                                     wqkvh, wqkvl, woh, wol, w1h, w1l, w2h, w2l);

    // 1. LN1 -> bf16 hi/lo
    ln_bf_kernel<<<ROWS, 256>>>(x, ln1g, ln1b, xnh, xnl);

    // 2. fused QKV projection with rope/vt epilogue (act=2)
    dim3 gQKV(3*Dsz/128, ROWS/128);
    bgemm<<<gQKV, 256, BG_SMEM>>>(xnh, xnl, wqkvh, wqkvl, nullptr, nullptr, nullptr,
                                  Dsz, 3*Dsz, nullptr, nullptr, 2, fc, fs, qb, kb, vt);

    // 3-6. flash attention -> ctx hi/lo
    flash_kernel<<<dim3(Ssz/128, Bsz*Hsz), 256, FSM_BYTES>>>(qb, kb, vt, ctxh, ctxl);

    // 7. x1 = x + ctx @ Wo + bo
    dim3 gQ(Dsz / 128, ROWS / 128);
    bgemm<<<gQ, 256, BG_SMEM>>>(ctxh, ctxl, woh, wol, x1, nullptr, nullptr,
                                Dsz, Dsz, bo, x, 0, nullptr, nullptr, nullptr, nullptr, nullptr);

    // 8. LN2 -> bf16 hi/lo
    ln_bf_kernel<<<ROWS, 256>>>(x1, ln2g, ln2b, xn2h, xn2l);

    // 9. h = gelu(xn2 @ W1 + b1) -> bf16 hi/lo
    dim3 gF1(DFFsz / 128, ROWS / 128);
    bgemm<<<gF1, 256, BG_SMEM>>>(xn2h, xn2l, w1h, w1l, nullptr, hh, hl,
                                 Dsz, DFFsz, b1, nullptr, 1, nullptr, nullptr, nullptr, nullptr, nullptr);

    // 10. out = x1 + h @ W2 + b2
    bgemm<<<gQ, 256, BG_SMEM>>>(hh, hl, w2h, w2l, out, nullptr, nullptr,
                                DFFsz, Dsz, b2, x1, 0, nullptr, nullptr, nullptr, nullptr, nullptr);
}

// round 16
// speedup vs baseline: 1.1061x; 1.0093x over previous
#include <cuda_runtime.h>
#include <cuda_bf16.h>
#include <math.h>
#include <stdint.h>

// Problem constants
#define Bsz   2
#define Ssz   2048
#define Dsz   1024
#define Hsz   16
#define HDsz  64
#define DFFsz 4096
#define ROWS  (Bsz*Ssz)
#define EPSLN 1e-5f
#define QSCL  0.18033688011112042f   // 0.125 * log2(e): softmax done in exp2 domain

// ---------------- scratch (device globals) ---------------------------------
__device__ float g_x1 [ROWS*Dsz];

__device__ __nv_bfloat16 g_xnh [ROWS*Dsz],  g_xnl [ROWS*Dsz];
__device__ __nv_bfloat16 g_xn2h[ROWS*Dsz],  g_xn2l[ROWS*Dsz];
__device__ __nv_bfloat16 g_ctxh[ROWS*Dsz],  g_ctxl[ROWS*Dsz];
__device__ __nv_bfloat16 g_hh  [ROWS*DFFsz], g_hl [ROWS*DFFsz];

__device__ __nv_bfloat16 g_qb[ROWS*Dsz];
__device__ __nv_bfloat16 g_kb[ROWS*Dsz];
__device__ __nv_bfloat16 g_vt[Bsz*Hsz*HDsz*Ssz];

__device__ __nv_bfloat16 g_wqkv_h[3*Dsz*Dsz], g_wqkv_l[3*Dsz*Dsz];
__device__ __nv_bfloat16 g_wo_h[Dsz*Dsz],  g_wo_l[Dsz*Dsz];
__device__ __nv_bfloat16 g_w1_h[Dsz*DFFsz], g_w1_l[Dsz*DFFsz];
__device__ __nv_bfloat16 g_w2_h[DFFsz*Dsz], g_w2_l[DFFsz*Dsz];

// ---------------- helpers ---------------------------------------------------
__device__ __forceinline__ uint32_t smem_u32(const void* p) {
    uint32_t a;
    asm("{ .reg .u64 t; cvta.to.shared.u64 t, %1; cvt.u32.u64 %0, t; }"
        : "=r"(a) : "l"(p));
    return a;
}
__device__ __forceinline__ void cpa16(uint32_t d, const void* s) {
    asm volatile("cp.async.cg.shared.global [%0], [%1], 16;" :: "r"(d), "l"(s));
}
#define CPA_COMMIT asm volatile("cp.async.commit_group;" ::: "memory")
#define CPA_WAIT(n) asm volatile("cp.async.wait_group %0;" :: "n"(n) : "memory")

__device__ __forceinline__ void ldm4(uint32_t* d, uint32_t a) {
    asm volatile("ldmatrix.sync.aligned.m8n8.x4.shared.b16 {%0,%1,%2,%3}, [%4];"
        : "=r"(d[0]), "=r"(d[1]), "=r"(d[2]), "=r"(d[3]) : "r"(a));
}
__device__ __forceinline__ float gelu_exact(float x) {
    return 0.5f * x * (1.0f + erff(x * 0.70710678118654752440f));
}
__device__ __forceinline__ uint32_t packbf(float x, float y) {
    uint32_t lo = __bfloat16_as_ushort(__float2bfloat16_rn(x));
    uint32_t hi = __bfloat16_as_ushort(__float2bfloat16_rn(y));
    return lo | (hi << 16);
}
__device__ __forceinline__ void mma16816(float* c, const uint32_t* a, const uint32_t* b) {
    asm volatile(
        "mma.sync.aligned.m16n8k16.row.col.f32.bf16.bf16.f32 "
        "{%0,%1,%2,%3}, {%4,%5,%6,%7}, {%8,%9}, {%0,%1,%2,%3};"
        : "+f"(c[0]), "+f"(c[1]), "+f"(c[2]), "+f"(c[3])
        : "r"(a[0]), "r"(a[1]), "r"(a[2]), "r"(a[3]), "r"(b[0]), "r"(b[1]));
}

__device__ __forceinline__ float block_sum(float v) {
    __shared__ float sh[8];
    int lane = threadIdx.x & 31, w = threadIdx.x >> 5;
    #pragma unroll
    for (int o = 16; o > 0; o >>= 1) v += __shfl_down_sync(0xffffffffu, v, o);
    if (!lane) sh[w] = v;
    __syncthreads();
    if (w == 0) {
        float t = (lane < 8) ? sh[lane] : 0.f;
        #pragma unroll
        for (int o = 4; o > 0; o >>= 1) t += __shfl_down_sync(0xffu, t, o);
        if (lane == 0) sh[0] = t;
    }
    __syncthreads();
    float r = sh[0];
    __syncthreads();
    return r;
}

// ---------------- layernorm -> bf16 hi/lo ----------------------------------
__global__ __launch_bounds__(256) void ln_bf_kernel(
    const float* __restrict__ x, const float* __restrict__ g,
    const float* __restrict__ b,
    __nv_bfloat16* __restrict__ oh, __nv_bfloat16* __restrict__ ol)
{
    int row = blockIdx.x, tid = threadIdx.x;
    const float* xr = x + (long long)row * Dsz;
    float4 v = *reinterpret_cast<const float4*>(xr + tid * 4);
    float mu = block_sum(v.x + v.y + v.z + v.w) * (1.0f / Dsz);
    float d0 = v.x - mu, d1 = v.y - mu, d2 = v.z - mu, d3 = v.w - mu;
    float var = block_sum(d0*d0 + d1*d1 + d2*d2 + d3*d3) * (1.0f / Dsz);
    float inv = rsqrtf(var + EPSLN);
    float4 gg = *reinterpret_cast<const float4*>(g + tid * 4);
    float4 bb = *reinterpret_cast<const float4*>(b + tid * 4);
    float o0 = d0 * inv * gg.x + bb.x;
    float o1 = d1 * inv * gg.y + bb.y;
    float o2 = d2 * inv * gg.z + bb.z;
    float o3 = d3 * inv * gg.w + bb.w;
    __nv_bfloat16 h0 = __float2bfloat16_rn(o0), h1 = __float2bfloat16_rn(o1);
    __nv_bfloat16 h2 = __float2bfloat16_rn(o2), h3 = __float2bfloat16_rn(o3);
    uint2 uh, ul;
    uh.x = (uint32_t)__bfloat16_as_ushort(h0) | ((uint32_t)__bfloat16_as_ushort(h1) << 16);
    uh.y = (uint32_t)__bfloat16_as_ushort(h2) | ((uint32_t)__bfloat16_as_ushort(h3) << 16);
    ul.x = packbf(o0 - __bfloat162float(h0), o1 - __bfloat162float(h1));
    ul.y = packbf(o2 - __bfloat162float(h2), o3 - __bfloat162float(h3));
    long long off = (long long)row * Dsz + tid * 4;
    *reinterpret_cast<uint2*>(oh + off) = uh;
    *reinterpret_cast<uint2*>(ol + off) = ul;
}

// ---------------- merged weight transpose + bf16 hi/lo split ---------------
__global__ __launch_bounds__(256) void wconv_all_kernel(
    const float* __restrict__ Wq, const float* __restrict__ Wk,
    const float* __restrict__ Wv, const float* __restrict__ Wo,
    const float* __restrict__ W1, const float* __restrict__ W2,
    __nv_bfloat16* __restrict__ wqkvh, __nv_bfloat16* __restrict__ wqkvl,
    __nv_bfloat16* __restrict__ woh,   __nv_bfloat16* __restrict__ wol,
    __nv_bfloat16* __restrict__ w1h,   __nv_bfloat16* __restrict__ w1l,
    __nv_bfloat16* __restrict__ w2h,   __nv_bfloat16* __restrict__ w2l)
{
    int idx = blockIdx.x;
    const float* W; __nv_bfloat16 *Th, *Tl; int K, N, seg;
    if (idx < 4096) {
        K = Dsz; N = Dsz; seg = idx & 1023;
        int which = idx >> 10;
        if (which == 0) { W = Wq; Th = wqkvh;             Tl = wqkvl; }
        else if (which == 1) { W = Wk; Th = wqkvh + Dsz*Dsz;   Tl = wqkvl + Dsz*Dsz; }
        else if (which == 2) { W = Wv; Th = wqkvh + 2*Dsz*Dsz; Tl = wqkvl + 2*Dsz*Dsz; }
        else { W = Wo; Th = woh; Tl = wol; }
    } else if (idx < 8192) {
        K = Dsz; N = DFFsz; seg = idx - 4096; W = W1; Th = w1h; Tl = w1l;
    } else {
        K = DFFsz; N = Dsz; seg = idx - 8192; W = W2; Th = w2h; Tl = w2l;
    }
    int nBN = N / 32;
    int n0 = (seg % nBN) * 32, k0 = (seg / nBN) * 32;

    __shared__ float t[32][33];
    int tx = threadIdx.x & 31, ty = threadIdx.x >> 5;
    #pragma unroll
    for (int r = 0; r < 4; ++r)
        t[ty + r * 8][tx] = W[(size_t)(k0 + ty + r * 8) * N + n0 + tx];
    __syncthreads();
    #pragma unroll
    for (int r = 0; r < 4; ++r) {
        int n = n0 + ty + r * 8, k = k0 + tx;
        float w = t[tx][ty + r * 8];
        __nv_bfloat16 hi = __float2bfloat16_rn(w);
        __nv_bfloat16 lo = __float2bfloat16_rn(w - __bfloat162float(hi));
        Th[(size_t)n * K + k] = hi;
        Tl[(size_t)n * K + k] = lo;
    }
}

// ---------------- bf16 GEMM: cp.async + ldmatrix, 2 CTAs/SM ----------------
// terms: 3 = Ah*Bh + Ah*Bl + Al*Bh (full split), 2 = Ah*Bh + Ah*Bl (A rounded)
// act: 0 = plain, 1 = gelu, 2 = fused QKV epilogue (rope->qb/kb, transpose->vt)
#define PADK     40
#define AH_OFF   0
#define AL_OFF   5120
#define BH_OFF   10240
#define BL_OFF   15360
#define SSTRIDE  20480
#define BG_SMEM  (2 * SSTRIDE * 2)

__global__ __launch_bounds__(256, 2) void bgemm(
    const __nv_bfloat16* __restrict__ Ah, const __nv_bfloat16* __restrict__ Al,
    const __nv_bfloat16* __restrict__ Bh, const __nv_bfloat16* __restrict__ Bl,
    float* __restrict__ C,
    __nv_bfloat16* __restrict__ Oh, __nv_bfloat16* __restrict__ Ol,
    int K, int N, int terms,
    const float* __restrict__ bias, const float* __restrict__ resid, int act,
    const float* __restrict__ fc, const float* __restrict__ fs,
    __nv_bfloat16* __restrict__ qb, __nv_bfloat16* __restrict__ kb,
    __nv_bfloat16* __restrict__ vt)
{
    extern __shared__ unsigned short sm[];
    uint32_t smB = smem_u32(sm);
    int tid = threadIdx.x, lane = tid & 31, wid = tid >> 5;
    int wr = wid >> 2, wc = wid & 3;
    int gid = lane >> 2, tig = lane & 3;
    int laneRow = lane & 7, lt = lane >> 3;
    int tileN = blockIdx.x * 128, tileM = blockIdx.y * 128;

    const __nv_bfloat16* Ahb = Ah + (size_t)tileM * K;
    const __nv_bfloat16* Alb = Al + (size_t)tileM * K;
    const __nv_bfloat16* Bhb = Bh + (size_t)tileN * K;
    const __nv_bfloat16* Blb = Bl + (size_t)tileN * K;

    float acc[4][4][4];
    #pragma unroll
    for (int mf = 0; mf < 4; ++mf)
        #pragma unroll
        for (int nf = 0; nf < 4; ++nf)
            #pragma unroll
            for (int i = 0; i < 4; ++i) acc[mf][nf][i] = 0.f;

    uint32_t aoff = (uint32_t)((wr * 64 + laneRow + ((lt & 1) ? 8 : 0)) * PADK
                               + ((lt & 2) ? 8 : 0));
    uint32_t boff = (uint32_t)((wc * 32 + laneRow + ((lt & 2) ? 8 : 0)) * PADK
                               + ((lt & 1) ? 8 : 0));

    int row0 = tid >> 2, c4 = tid & 3;
    int row1 = row0 + 64;

    int nCh = K >> 5;

    {
        uint32_t sb = smB;
        uint32_t d0 = (uint32_t)(row0 * PADK + c4 * 8) * 2;
        uint32_t d1 = (uint32_t)(row1 * PADK + c4 * 8) * 2;
        size_t s0 = (size_t)row0 * K + c4 * 8;
        size_t s1 = (size_t)row1 * K + c4 * 8;
        cpa16(sb + AH_OFF*2 + d0, Ahb + s0); cpa16(sb + AH_OFF*2 + d1, Ahb + s1);
        if (terms == 3) {
            cpa16(sb + AL_OFF*2 + d0, Alb + s0); cpa16(sb + AL_OFF*2 + d1, Alb + s1);
        }
        cpa16(sb + BH_OFF*2 + d0, Bhb + s0); cpa16(sb + BH_OFF*2 + d1, Bhb + s1);
        cpa16(sb + BL_OFF*2 + d0, Blb + s0); cpa16(sb + BL_OFF*2 + d1, Blb + s1);
        CPA_COMMIT;
    }

    for (int c = 0; c < nCh; ++c) {
        int s = c & 1;
        if (c + 1 < nCh) {
            int k0 = (c + 1) << 5;
            uint32_t sb = smB + (uint32_t)(s ^ 1) * (SSTRIDE * 2);
            uint32_t d0 = (uint32_t)(row0 * PADK + c4 * 8) * 2;
            uint32_t d1 = (uint32_t)(row1 * PADK + c4 * 8) * 2;
            size_t s0 = (size_t)row0 * K + k0 + c4 * 8;
            size_t s1 = (size_t)row1 * K + k0 + c4 * 8;
            cpa16(sb + AH_OFF*2 + d0, Ahb + s0); cpa16(sb + AH_OFF*2 + d1, Ahb + s1);
            if (terms == 3) {
                cpa16(sb + AL_OFF*2 + d0, Alb + s0); cpa16(sb + AL_OFF*2 + d1, Alb + s1);
            }
            cpa16(sb + BH_OFF*2 + d0, Bhb + s0); cpa16(sb + BH_OFF*2 + d1, Bhb + s1);
            cpa16(sb + BL_OFF*2 + d0, Blb + s0); cpa16(sb + BL_OFF*2 + d1, Blb + s1);
            CPA_COMMIT;
            CPA_WAIT(1);
        } else {
            CPA_WAIT(0);
        }
        __syncthreads();

        uint32_t stb = smB + (uint32_t)s * (SSTRIDE * 2);
        #pragma unroll
        for (int kk = 0; kk < 32; kk += 16) {
            uint32_t ah[4][4], al[4][4], bh[4][2], bl[4][2];
            #pragma unroll
            for (int mf = 0; mf < 4; ++mf) {
                uint32_t ad = stb + 2u * (aoff + (uint32_t)(mf * 16 * PADK + kk));
                ldm4(ah[mf], ad + 2u * AH_OFF);
                if (terms == 3) ldm4(al[mf], ad + 2u * AL_OFF);
            }
            #pragma unroll
            for (int np = 0; np < 2; ++np) {
                uint32_t bd = stb + 2u * (boff + (uint32_t)(np * 16 * PADK + kk));
                uint32_t t4[4];
                ldm4(t4, bd + 2u * BH_OFF);
                bh[2*np][0] = t4[0]; bh[2*np][1] = t4[1];
                bh[2*np+1][0] = t4[2]; bh[2*np+1][1] = t4[3];
                ldm4(t4, bd + 2u * BL_OFF);
                bl[2*np][0] = t4[0]; bl[2*np][1] = t4[1];
                bl[2*np+1][0] = t4[2]; bl[2*np+1][1] = t4[3];
            }
            #pragma unroll
            for (int mf = 0; mf < 4; ++mf)
                #pragma unroll
                for (int nf = 0; nf < 4; ++nf) {
                    mma16816(acc[mf][nf], ah[mf], bh[nf]);
                    mma16816(acc[mf][nf], ah[mf], bl[nf]);
                    if (terms == 3) mma16816(acc[mf][nf], al[mf], bh[nf]);
                }
        }
        __syncthreads();
    }

    // ---- epilogue ----
    if (act == 2) {
        // fused QKV: rope -> qb/kb (Q scaled to exp2 domain), transpose -> vt.
        #pragma unroll
        for (int mf = 0; mf < 4; ++mf) {
            int row = tileM + wr * 64 + mf * 16 + gid;
            #pragma unroll
            for (int nf = 0; nf < 4; ++nf) {
                int col = tileN + wc * 32 + nf * 8 + 2 * tig;
                #pragma unroll
                for (int half = 0; half < 2; ++half) {
                    int r = row + half * 8;
                    float e = acc[mf][nf][2*half];
                    float o = acc[mf][nf][2*half + 1];
                    int srow = r & (Ssz - 1);
                    if (col < Dsz) {
                        int i = (col & 63) >> 1;
                        float cv = fc[srow * 32 + i], sv = fs[srow * 32 + i];
                        float r0 = (e * cv - o * sv) * QSCL;
                        float r1 = (e * sv + o * cv) * QSCL;
                        __nv_bfloat162 p;
                        p.x = __float2bfloat16_rn(r0); p.y = __float2bfloat16_rn(r1);
                        *reinterpret_cast<__nv_bfloat162*>(qb + (size_t)r * Dsz + col) = p;
                    } else if (col < 2 * Dsz) {
                        int cc = col - Dsz;
                        int i = (cc & 63) >> 1;
                        float cv = fc[srow * 32 + i], sv = fs[srow * 32 + i];
                        float r0 = e * cv - o * sv;
                        float r1 = e * sv + o * cv;
                        __nv_bfloat162 p;
                        p.x = __float2bfloat16_rn(r0); p.y = __float2bfloat16_rn(r1);
                        *reinterpret_cast<__nv_bfloat162*>(kb + (size_t)r * Dsz + cc) = p;
                    } else {
                        int cc = col - 2 * Dsz;
                        int h = cc >> 6, n = cc & 63;
                        int bh = (r >> 11) * Hsz + h;
                        size_t base = ((size_t)bh * HDsz) * Ssz + srow;
                        vt[base + (size_t)n * Ssz]       = __float2bfloat16_rn(e);
                        vt[base + (size_t)(n + 1) * Ssz] = __float2bfloat16_rn(o);
                    }
                }
            }
        }
        return;
    }

    #pragma unroll
    for (int mf = 0; mf < 4; ++mf) {
        int row = tileM + wr * 64 + mf * 16 + gid;
        #pragma unroll
        for (int nf = 0; nf < 4; ++nf) {
            int col = tileN + wc * 32 + nf * 8 + 2 * tig;
            float2 v0 = make_float2(acc[mf][nf][0], acc[mf][nf][1]);
            float2 v1 = make_float2(acc[mf][nf][2], acc[mf][nf][3]);
            if (bias) {
                float2 bv = *reinterpret_cast<const float2*>(bias + col);
                v0.x += bv.x; v0.y += bv.y;
                v1.x += bv.x; v1.y += bv.y;
            }
            if (act == 1) {
                v0.x = gelu_exact(v0.x); v0.y = gelu_exact(v0.y);
                v1.x = gelu_exact(v1.x); v1.y = gelu_exact(v1.y);
            }
            size_t i0 = (size_t)row * N + col;
            size_t i1 = (size_t)(row + 8) * N + col;
            if (resid) {
                float2 r0 = *reinterpret_cast<const float2*>(resid + i0);
                float2 r1 = *reinterpret_cast<const float2*>(resid + i1);
                v0.x += r0.x; v0.y += r0.y;
                v1.x += r1.x; v1.y += r1.y;
            }
            if (C) {
                *reinterpret_cast<float2*>(C + i0) = v0;
                *reinterpret_cast<float2*>(C + i1) = v1;
            }
            if (Oh) {
                __nv_bfloat16 h0 = __float2bfloat16_rn(v0.x), h1 = __float2bfloat16_rn(v0.y);
                __nv_bfloat16 h2 = __float2bfloat16_rn(v1.x), h3 = __float2bfloat16_rn(v1.y);
                uint32_t uh0 = (uint32_t)__bfloat16_as_ushort(h0) | ((uint32_t)__bfloat16_as_ushort(h1) << 16);
                uint32_t uh1 = (uint32_t)__bfloat16_as_ushort(h2) | ((uint32_t)__bfloat16_as_ushort(h3) << 16);
                uint32_t ul0 = packbf(v0.x - __bfloat162float(h0), v0.y - __bfloat162float(h1));
                uint32_t ul1 = packbf(v1.x - __bfloat162float(h2), v1.y - __bfloat162float(h3));
                *reinterpret_cast<uint32_t*>(Oh + i0) = uh0;
                *reinterpret_cast<uint32_t*>(Oh + i1) = uh1;
                *reinterpret_cast<uint32_t*>(Ol + i0) = ul0;
                *reinterpret_cast<uint32_t*>(Ol + i1) = ul1;
            }
        }
    }
}

// ---------------- fused flash attention (2 CTAs/SM, exp2 softmax) ----------
#define FQS 72
#define FVS 136
#define FQ_OFF 0
#define FK_OFF 9216
#define FV_OFF (9216 + 2*9216)
#define FSM_BYTES ((FV_OFF + 2*8704) * 2)

__global__ __launch_bounds__(256, 2) void flash_kernel(
    const __nv_bfloat16* __restrict__ Qb, const __nv_bfloat16* __restrict__ Kb,
    const __nv_bfloat16* __restrict__ Vt,
    __nv_bfloat16* __restrict__ ctxh, __nv_bfloat16* __restrict__ ctxl)
{
    extern __shared__ unsigned short fsm[];
    uint32_t smB = smem_u32(fsm);
    int tid = threadIdx.x, lane = tid & 31, w = tid >> 5;
    int gid = lane >> 2, tig = lane & 3;
    int laneRow = lane & 7, lt = lane >> 3;
    int tq = blockIdx.x, bh = blockIdx.y;
    int b = bh >> 4, h = bh & 15;

    size_t qRow0 = (size_t)b * Ssz + tq * 128;
    const __nv_bfloat16* Qg = Qb + qRow0 * Dsz + h * HDsz;
    const __nv_bfloat16* Kg = Kb + ((size_t)b * Ssz) * Dsz + h * HDsz;
    const __nv_bfloat16* Vg = Vt + ((size_t)bh * HDsz) * Ssz;

    #pragma unroll
    for (int i = 0; i < 4; ++i) {
        int idx = tid + i * 256; int r = idx >> 3, c = idx & 7;
        cpa16(smB + (FQ_OFF + r * FQS) * 2 + c * 16, Qg + (size_t)r * Dsz + c * 8);
    }
    #pragma unroll
    for (int i = 0; i < 4; ++i) {
        int idx = tid + i * 256; int r = idx >> 3, c = idx & 7;
        cpa16(smB + (FK_OFF + r * FQS) * 2 + c * 16, Kg + (size_t)r * Dsz + c * 8);
    }
    #pragma unroll
    for (int i = 0; i < 4; ++i) {
        int idx = tid + i * 256; int n = idx >> 4, c = idx & 15;
        cpa16(smB + (FV_OFF + n * FVS) * 2 + c * 16, Vg + (size_t)n * Ssz + c * 8);
    }
    CPA_COMMIT;

    uint32_t qoff = (uint32_t)((w * 16 + laneRow + ((lt & 1) ? 8 : 0)) * FQS
                               + ((lt & 2) ? 8 : 0));
    uint32_t koff = (uint32_t)((laneRow + ((lt & 2) ? 8 : 0)) * FQS
                               + ((lt & 1) ? 8 : 0));
    uint32_t voff = (uint32_t)((laneRow + ((lt & 2) ? 8 : 0)) * FVS
                               + ((lt & 1) ? 8 : 0));

    float m0 = -1e30f, m1 = -1e30f, l0 = 0.f, l1 = 0.f;
    float ctx[8][4];
    #pragma unroll
    for (int nf = 0; nf < 8; ++nf)
        #pragma unroll
        for (int i = 0; i < 4; ++i) ctx[nf][i] = 0.f;

    int st = 0;
    for (int t = 0; t < 16; ++t) {
        if (t + 1 < 16) {
            int s2 = st ^ 1;
            #pragma unroll
            for (int i = 0; i < 4; ++i) {
                int idx = tid + i * 256; int r = idx >> 3, c = idx & 7;
                cpa16(smB + (FK_OFF + s2 * 9216 + r * FQS) * 2 + c * 16,
                      Kg + ((size_t)((t + 1) * 128 + r)) * Dsz + c * 8);
            }
            #pragma unroll
            for (int i = 0; i < 4; ++i) {
                int idx = tid + i * 256; int n = idx >> 4, c = idx & 15;
                cpa16(smB + (FV_OFF + s2 * 8704 + n * FVS) * 2 + c * 16,
                      Vg + (size_t)n * Ssz + (t + 1) * 128 + c * 8);
            }
            CPA_COMMIT;
            CPA_WAIT(1);
        } else {
            CPA_WAIT(0);
        }
        __syncthreads();

        uint32_t Qsb = smB + FQ_OFF * 2;
        uint32_t Ksb = smB + (FK_OFF + st * 9216) * 2;
        uint32_t Vsb = smB + (FV_OFF + st * 8704) * 2;

        // ---- S = Q K^T (scores already in log2 domain via QSCL) ----
        float s4[16][4];
        #pragma unroll
        for (int nf = 0; nf < 16; ++nf)
            #pragma unroll
            for (int i = 0; i < 4; ++i) s4[nf][i] = 0.f;

        #pragma unroll
        for (int kk = 0; kk < 64; kk += 16) {
            uint32_t a[4];
            ldm4(a, Qsb + 2u * (qoff + kk));
            #pragma unroll
            for (int np = 0; np < 8; ++np) {
                uint32_t t4[4];
                ldm4(t4, Ksb + 2u * (koff + (uint32_t)(np * 16 * FQS + kk)));
                mma16816(s4[2*np],     a, t4);
                mma16816(s4[2*np + 1], a, t4 + 2);
            }
        }

        // ---- online softmax (exp2 domain) ----
        float mx0 = -1e30f, mx1 = -1e30f;
        #pragma unroll
        for (int nf = 0; nf < 16; ++nf) {
            mx0 = fmaxf(mx0, fmaxf(s4[nf][0], s4[nf][1]));
            mx1 = fmaxf(mx1, fmaxf(s4[nf][2], s4[nf][3]));
        }
        mx0 = fmaxf(mx0, __shfl_xor_sync(0xffffffffu, mx0, 1));
        mx0 = fmaxf(mx0, __shfl_xor_sync(0xffffffffu, mx0, 2));
        mx1 = fmaxf(mx1, __shfl_xor_sync(0xffffffffu, mx1, 1));
        mx1 = fmaxf(mx1, __shfl_xor_sync(0xffffffffu, mx1, 2));
        float mn0 = fmaxf(m0, mx0), mn1 = fmaxf(m1, mx1);
        float al0 = exp2f(m0 - mn0), al1 = exp2f(m1 - mn1);
        float sum0 = 0.f, sum1 = 0.f;
        #pragma unroll
        for (int nf = 0; nf < 16; ++nf) {
            s4[nf][0] = exp2f(s4[nf][0] - mn0);
            s4[nf][1] = exp2f(s4[nf][1] - mn0);
            s4[nf][2] = exp2f(s4[nf][2] - mn1);
            s4[nf][3] = exp2f(s4[nf][3] - mn1);
            sum0 += s4[nf][0] + s4[nf][1];
            sum1 += s4[nf][2] + s4[nf][3];
        }
        sum0 += __shfl_xor_sync(0xffffffffu, sum0, 1);
        sum0 += __shfl_xor_sync(0xffffffffu, sum0, 2);
        sum1 += __shfl_xor_sync(0xffffffffu, sum1, 1);
        sum1 += __shfl_xor_sync(0xffffffffu, sum1, 2);
        l0 = l0 * al0 + sum0; l1 = l1 * al1 + sum1;
        m0 = mn0; m1 = mn1;
        #pragma unroll
        for (int nf = 0; nf < 8; ++nf) {
            ctx[nf][0] *= al0; ctx[nf][1] *= al0;
            ctx[nf][2] *= al1; ctx[nf][3] *= al1;
        }

        // ---- ctx += P @ V ----
        #pragma unroll
        for (int kc = 0; kc < 8; ++kc) {
            uint32_t a[4];
            a[0] = packbf(s4[2*kc][0],   s4[2*kc][1]);
            a[1] = packbf(s4[2*kc][2],   s4[2*kc][3]);
            a[2] = packbf(s4[2*kc+1][0], s4[2*kc+1][1]);
            a[3] = packbf(s4[2*kc+1][2], s4[2*kc+1][3]);
            #pragma unroll
            for (int np = 0; np < 4; ++np) {
                uint32_t t4[4];
                ldm4(t4, Vsb + 2u * (voff + (uint32_t)(np * 16 * FVS + kc * 16)));
                mma16816(ctx[2*np],     a, t4);
                mma16816(ctx[2*np + 1], a, t4 + 2);
            }
        }

        __syncthreads();
        st ^= 1;
    }

    float i0 = 1.f / l0, i1 = 1.f / l1;
    size_t rbase = (qRow0 + w * 16 + gid) * Dsz + h * HDsz;
    #pragma unroll
    for (int nf = 0; nf < 8; ++nf) {
        int col = nf * 8 + 2 * tig;
        float v00 = ctx[nf][0] * i0, v01 = ctx[nf][1] * i0;
        float v10 = ctx[nf][2] * i1, v11 = ctx[nf][3] * i1;
        __nv_bfloat16 h00 = __float2bfloat16_rn(v00), h01 = __float2bfloat16_rn(v01);
        __nv_bfloat16 h10 = __float2bfloat16_rn(v10), h11 = __float2bfloat16_rn(v11);
        uint32_t uh0 = (uint32_t)__bfloat16_as_ushort(h00) | ((uint32_t)__bfloat16_as_ushort(h01) << 16);
        uint32_t uh1 = (uint32_t)__bfloat16_as_ushort(h10) | ((uint32_t)__bfloat16_as_ushort(h11) << 16);
        uint32_t ul0 = packbf(v00 - __bfloat162float(h00), v01 - __bfloat162float(h01));
        uint32_t ul1 = packbf(v10 - __bfloat162float(h10), v11 - __bfloat162float(h11));
        *reinterpret_cast<uint32_t*>(ctxh + rbase + col) = uh0;
        *reinterpret_cast<uint32_t*>(ctxh + rbase + (size_t)8 * Dsz + col) = uh1;
        *reinterpret_cast<uint32_t*>(ctxl + rbase + col) = ul0;
        *reinterpret_cast<uint32_t*>(ctxl + rbase + (size_t)8 * Dsz + col) = ul1;
    }
}

// ---------------- launch ----------------------------------------------------
extern "C" void kernel_launch(void* const* d_in, const int* in_sizes, int n_in,
                              void* d_out, int out_size)
{
    const float* x    = (const float*)d_in[0];
    const float* fc   = (const float*)d_in[2];
    const float* fs   = (const float*)d_in[3];
    const float* Wq   = (const float*)d_in[4];
    const float* Wk   = (const float*)d_in[5];
    const float* Wv   = (const float*)d_in[6];
    const float* Wo   = (const float*)d_in[7];
    const float* bo   = (const float*)d_in[8];
    const float* ln1g = (const float*)d_in[9];
    const float* ln1b = (const float*)d_in[10];
    const float* ln2g = (const float*)d_in[11];
    const float* ln2b = (const float*)d_in[12];
    const float* W1   = (const float*)d_in[13];
    const float* b1   = (const float*)d_in[14];
    const float* W2   = (const float*)d_in[15];
    const float* b2   = (const float*)d_in[16];
    float* out = (float*)d_out;

    float *x1;
    cudaGetSymbolAddress((void**)&x1, g_x1);

    __nv_bfloat16 *xnh,*xnl,*xn2h,*xn2l,*ctxh,*ctxl,*hh,*hl,*qb,*kb,*vt;
    cudaGetSymbolAddress((void**)&xnh,  g_xnh);  cudaGetSymbolAddress((void**)&xnl,  g_xnl);
    cudaGetSymbolAddress((void**)&xn2h, g_xn2h); cudaGetSymbolAddress((void**)&xn2l, g_xn2l);
    cudaGetSymbolAddress((void**)&ctxh, g_ctxh); cudaGetSymbolAddress((void**)&ctxl, g_ctxl);
    cudaGetSymbolAddress((void**)&hh,   g_hh);   cudaGetSymbolAddress((void**)&hl,   g_hl);
    cudaGetSymbolAddress((void**)&qb,   g_qb);
    cudaGetSymbolAddress((void**)&kb,   g_kb);
    cudaGetSymbolAddress((void**)&vt,   g_vt);

    __nv_bfloat16 *wqkvh,*wqkvl,*woh,*wol,*w1h,*w1l,*w2h,*w2l;
    cudaGetSymbolAddress((void**)&wqkvh, g_wqkv_h); cudaGetSymbolAddress((void**)&wqkvl, g_wqkv_l);
    cudaGetSymbolAddress((void**)&woh, g_wo_h); cudaGetSymbolAddress((void**)&wol, g_wo_l);
    cudaGetSymbolAddress((void**)&w1h, g_w1_h); cudaGetSymbolAddress((void**)&w1l, g_w1_l);
    cudaGetSymbolAddress((void**)&w2h, g_w2_h); cudaGetSymbolAddress((void**)&w2l, g_w2_l);

    cudaFuncSetAttribute(bgemm, cudaFuncAttributeMaxDynamicSharedMemorySize, BG_SMEM);
    cudaFuncSetAttribute(flash_kernel, cudaFuncAttributeMaxDynamicSharedMemorySize, FSM_BYTES);

    // 0. all weight conversions in one launch
    wconv_all_kernel<<<12288, 256>>>(Wq, Wk, Wv, Wo, W1, W2,
                                     wqkvh, wqkvl, woh, wol, w1h, w1l, w2h, w2l);

    // 1. LN1 -> bf16 hi/lo
    ln_bf_kernel<<<ROWS, 256>>>(x, ln1g, ln1b, xnh, xnl);

    // 2. fused QKV projection (2-term: q/k/v are rounded to bf16 right after
    //    anyway, so the dropped Al*Bh term is below the storage precision)
    dim3 gQKV(3*Dsz/128, ROWS/128);
    bgemm<<<gQKV, 256, BG_SMEM>>>(xnh, xnl, wqkvh, wqkvl, nullptr, nullptr, nullptr,
                                  Dsz, 3*Dsz, 2, nullptr, nullptr, 2, fc, fs, qb, kb, vt);

    // 3-6. flash attention -> ctx hi/lo
    flash_kernel<<<dim3(Ssz/128, Bsz*Hsz), 256, FSM_BYTES>>>(qb, kb, vt, ctxh, ctxl);

    // 7. x1 = x + ctx @ Wo + bo (2-term: attention-path output sensitivity is
    //    measured at 1.7e-2 per unit relative -> 2e-3 error contributes ~3e-5)
    dim3 gQ(Dsz / 128, ROWS / 128);
    bgemm<<<gQ, 256, BG_SMEM>>>(ctxh, ctxl, woh, wol, x1, nullptr, nullptr,
                                Dsz, Dsz, 2, bo, x, 0, nullptr, nullptr, nullptr, nullptr, nullptr);

    // 8. LN2 -> bf16 hi/lo
    ln_bf_kernel<<<ROWS, 256>>>(x1, ln2g, ln2b, xn2h, xn2l);

    // 9. h = gelu(xn2 @ W1 + b1) -> bf16 hi/lo  (3-term: FFN path needs precision)
    dim3 gF1(DFFsz / 128, ROWS / 128);
    bgemm<<<gF1, 256, BG_SMEM>>>(xn2h, xn2l, w1h, w1l, nullptr, hh, hl,
                                 Dsz, DFFsz, 3, b1, nullptr, 1, nullptr, nullptr, nullptr, nullptr, nullptr);

    // 10. out = x1 + h @ W2 + b2  (3-term)
    bgemm<<<gQ, 256, BG_SMEM>>>(hh, hl, w2h, w2l, out, nullptr, nullptr,
                                DFFsz, Dsz, 3, b2, x1, 0, nullptr, nullptr, nullptr, nullptr, nullptr);
}

// round 17
// speedup vs baseline: 1.2134x; 1.0970x over previous
#include <cuda_runtime.h>
#include <cuda_bf16.h>
#include <math.h>
#include <stdint.h>

// Problem constants
#define Bsz   2
#define Ssz   2048
#define Dsz   1024
#define Hsz   16
#define HDsz  64
#define DFFsz 4096
#define ROWS  (Bsz*Ssz)
#define EPSLN 1e-5f
#define QSCL  0.18033688011112042f   // 0.125 * log2(e): softmax done in exp2 domain

// ---------------- scratch (device globals) ---------------------------------
__device__ float g_x1 [ROWS*Dsz];

__device__ __nv_bfloat16 g_xnh [ROWS*Dsz],  g_xnl [ROWS*Dsz];
__device__ __nv_bfloat16 g_xn2h[ROWS*Dsz],  g_xn2l[ROWS*Dsz];
__device__ __nv_bfloat16 g_ctxh[ROWS*Dsz],  g_ctxl[ROWS*Dsz];
__device__ __nv_bfloat16 g_hh  [ROWS*DFFsz], g_hl [ROWS*DFFsz];

__device__ __nv_bfloat16 g_qb[ROWS*Dsz];
__device__ __nv_bfloat16 g_kb[ROWS*Dsz];
__device__ __nv_bfloat16 g_vt[Bsz*Hsz*HDsz*Ssz];

__device__ __nv_bfloat16 g_wqkv_h[3*Dsz*Dsz], g_wqkv_l[3*Dsz*Dsz];
__device__ __nv_bfloat16 g_wo_h[Dsz*Dsz],  g_wo_l[Dsz*Dsz];
__device__ __nv_bfloat16 g_w1_h[Dsz*DFFsz], g_w1_l[Dsz*DFFsz];
__device__ __nv_bfloat16 g_w2_h[DFFsz*Dsz], g_w2_l[DFFsz*Dsz];

// ---------------- helpers ---------------------------------------------------
__device__ __forceinline__ uint32_t smem_u32(const void* p) {
    uint32_t a;
    asm("{ .reg .u64 t; cvta.to.shared.u64 t, %1; cvt.u32.u64 %0, t; }"
        : "=r"(a) : "l"(p));
    return a;
}
__device__ __forceinline__ void cpa16(uint32_t d, const void* s) {
    asm volatile("cp.async.cg.shared.global [%0], [%1], 16;" :: "r"(d), "l"(s));
}
#define CPA_COMMIT asm volatile("cp.async.commit_group;" ::: "memory")
#define CPA_WAIT(n) asm volatile("cp.async.wait_group %0;" :: "n"(n) : "memory")

__device__ __forceinline__ void ldm4(uint32_t* d, uint32_t a) {
    asm volatile("ldmatrix.sync.aligned.m8n8.x4.shared.b16 {%0,%1,%2,%3}, [%4];"
        : "=r"(d[0]), "=r"(d[1]), "=r"(d[2]), "=r"(d[3]) : "r"(a));
}
__device__ __forceinline__ float gelu_exact(float x) {
    return 0.5f * x * (1.0f + erff(x * 0.70710678118654752440f));
}
__device__ __forceinline__ uint32_t packbf(float x, float y) {
    uint32_t lo = __bfloat16_as_ushort(__float2bfloat16_rn(x));
    uint32_t hi = __bfloat16_as_ushort(__float2bfloat16_rn(y));
    return lo | (hi << 16);
}
__device__ __forceinline__ void mma16816(float* c, const uint32_t* a, const uint32_t* b) {
    asm volatile(
        "mma.sync.aligned.m16n8k16.row.col.f32.bf16.bf16.f32 "
        "{%0,%1,%2,%3}, {%4,%5,%6,%7}, {%8,%9}, {%0,%1,%2,%3};"
        : "+f"(c[0]), "+f"(c[1]), "+f"(c[2]), "+f"(c[3])
        : "r"(a[0]), "r"(a[1]), "r"(a[2]), "r"(a[3]), "r"(b[0]), "r"(b[1]));
}

__device__ __forceinline__ float block_sum(float v) {
    __shared__ float sh[8];
    int lane = threadIdx.x & 31, w = threadIdx.x >> 5;
    #pragma unroll
    for (int o = 16; o > 0; o >>= 1) v += __shfl_down_sync(0xffffffffu, v, o);
    if (!lane) sh[w] = v;
    __syncthreads();
    if (w == 0) {
        float t = (lane < 8) ? sh[lane] : 0.f;
        #pragma unroll
        for (int o = 4; o > 0; o >>= 1) t += __shfl_down_sync(0xffu, t, o);
        if (lane == 0) sh[0] = t;
    }
    __syncthreads();
    float r = sh[0];
    __syncthreads();
    return r;
}

// ---------------- layernorm -> bf16 hi/lo ----------------------------------
__global__ __launch_bounds__(256) void ln_bf_kernel(
    const float* __restrict__ x, const float* __restrict__ g,
    const float* __restrict__ b,
    __nv_bfloat16* __restrict__ oh, __nv_bfloat16* __restrict__ ol)
{
    int row = blockIdx.x, tid = threadIdx.x;
    const float* xr = x + (long long)row * Dsz;
    float4 v = *reinterpret_cast<const float4*>(xr + tid * 4);
    float mu = block_sum(v.x + v.y + v.z + v.w) * (1.0f / Dsz);
    float d0 = v.x - mu, d1 = v.y - mu, d2 = v.z - mu, d3 = v.w - mu;
    float var = block_sum(d0*d0 + d1*d1 + d2*d2 + d3*d3) * (1.0f / Dsz);
    float inv = rsqrtf(var + EPSLN);
    float4 gg = *reinterpret_cast<const float4*>(g + tid * 4);
    float4 bb = *reinterpret_cast<const float4*>(b + tid * 4);
    float o0 = d0 * inv * gg.x + bb.x;
    float o1 = d1 * inv * gg.y + bb.y;
    float o2 = d2 * inv * gg.z + bb.z;
    float o3 = d3 * inv * gg.w + bb.w;
    __nv_bfloat16 h0 = __float2bfloat16_rn(o0), h1 = __float2bfloat16_rn(o1);
    __nv_bfloat16 h2 = __float2bfloat16_rn(o2), h3 = __float2bfloat16_rn(o3);
    uint2 uh, ul;
    uh.x = (uint32_t)__bfloat16_as_ushort(h0) | ((uint32_t)__bfloat16_as_ushort(h1) << 16);
    uh.y = (uint32_t)__bfloat16_as_ushort(h2) | ((uint32_t)__bfloat16_as_ushort(h3) << 16);
    ul.x = packbf(o0 - __bfloat162float(h0), o1 - __bfloat162float(h1));
    ul.y = packbf(o2 - __bfloat162float(h2), o3 - __bfloat162float(h3));
    long long off = (long long)row * Dsz + tid * 4;
    *reinterpret_cast<uint2*>(oh + off) = uh;
    *reinterpret_cast<uint2*>(ol + off) = ul;
}

// ---------------- merged weight transpose + bf16 hi/lo split ---------------
__global__ __launch_bounds__(256) void wconv_all_kernel(
    const float* __restrict__ Wq, const float* __restrict__ Wk,
    const float* __restrict__ Wv, const float* __restrict__ Wo,
    const float* __restrict__ W1, const float* __restrict__ W2,
    __nv_bfloat16* __restrict__ wqkvh, __nv_bfloat16* __restrict__ wqkvl,
    __nv_bfloat16* __restrict__ woh,   __nv_bfloat16* __restrict__ wol,
    __nv_bfloat16* __restrict__ w1h,   __nv_bfloat16* __restrict__ w1l,
    __nv_bfloat16* __restrict__ w2h,   __nv_bfloat16* __restrict__ w2l)
{
    int idx = blockIdx.x;
    const float* W; __nv_bfloat16 *Th, *Tl; int K, N, seg;
    if (idx < 4096) {
        K = Dsz; N = Dsz; seg = idx & 1023;
        int which = idx >> 10;
        if (which == 0) { W = Wq; Th = wqkvh;             Tl = wqkvl; }
        else if (which == 1) { W = Wk; Th = wqkvh + Dsz*Dsz;   Tl = wqkvl + Dsz*Dsz; }
        else if (which == 2) { W = Wv; Th = wqkvh + 2*Dsz*Dsz; Tl = wqkvl + 2*Dsz*Dsz; }
        else { W = Wo; Th = woh; Tl = wol; }
    } else if (idx < 8192) {
        K = Dsz; N = DFFsz; seg = idx - 4096; W = W1; Th = w1h; Tl = w1l;
    } else {
        K = DFFsz; N = Dsz; seg = idx - 8192; W = W2; Th = w2h; Tl = w2l;
    }
    int nBN = N / 32;
    int n0 = (seg % nBN) * 32, k0 = (seg / nBN) * 32;

    __shared__ float t[32][33];
    int tx = threadIdx.x & 31, ty = threadIdx.x >> 5;
    #pragma unroll
    for (int r = 0; r < 4; ++r)
        t[ty + r * 8][tx] = W[(size_t)(k0 + ty + r * 8) * N + n0 + tx];
    __syncthreads();
    #pragma unroll
    for (int r = 0; r < 4; ++r) {
        int n = n0 + ty + r * 8, k = k0 + tx;
        float w = t[tx][ty + r * 8];
        __nv_bfloat16 hi = __float2bfloat16_rn(w);
        __nv_bfloat16 lo = __float2bfloat16_rn(w - __bfloat162float(hi));
        Th[(size_t)n * K + k] = hi;
        Tl[(size_t)n * K + k] = lo;
    }
}

// ---------------- bf16 GEMM: single-sync pipelined, 2 CTAs/SM --------------
// TERMS: 3 = Ah*Bh + Ah*Bl + Al*Bh, 2 = Ah*Bh + Ah*Bl (A-lo dropped)
// act: 0 = plain, 1 = gelu, 2 = fused QKV epilogue (rope->qb/kb, transpose->vt)
#define PADK     40
#define AH_OFF   0
#define AL_OFF   5120
#define BH_OFF   10240
#define BL_OFF   15360
#define SSTRIDE  20480
#define BG_SMEM  (2 * SSTRIDE * 2)

template<int TERMS>
__global__ __launch_bounds__(256, 2) void bgemm(
    const __nv_bfloat16* __restrict__ Ah, const __nv_bfloat16* __restrict__ Al,
    const __nv_bfloat16* __restrict__ Bh, const __nv_bfloat16* __restrict__ Bl,
    float* __restrict__ C,
    __nv_bfloat16* __restrict__ Oh, __nv_bfloat16* __restrict__ Ol,
    int K, int N,
    const float* __restrict__ bias, const float* __restrict__ resid, int act,
    const float* __restrict__ fc, const float* __restrict__ fs,
    __nv_bfloat16* __restrict__ qb, __nv_bfloat16* __restrict__ kb,
    __nv_bfloat16* __restrict__ vt)
{
    extern __shared__ unsigned short sm[];
    uint32_t smB = smem_u32(sm);
    int tid = threadIdx.x, lane = tid & 31, wid = tid >> 5;
    int wr = wid >> 2, wc = wid & 3;
    int gid = lane >> 2, tig = lane & 3;
    int laneRow = lane & 7, lt = lane >> 3;
    int tileN = blockIdx.x * 128, tileM = blockIdx.y * 128;

    const __nv_bfloat16* Ahb = Ah + (size_t)tileM * K;
    const __nv_bfloat16* Alb = Al + (size_t)tileM * K;
    const __nv_bfloat16* Bhb = Bh + (size_t)tileN * K;
    const __nv_bfloat16* Blb = Bl + (size_t)tileN * K;

    float acc[4][4][4];
    #pragma unroll
    for (int mf = 0; mf < 4; ++mf)
        #pragma unroll
        for (int nf = 0; nf < 4; ++nf)
            #pragma unroll
            for (int i = 0; i < 4; ++i) acc[mf][nf][i] = 0.f;

    uint32_t aoff = (uint32_t)((wr * 64 + laneRow + ((lt & 1) ? 8 : 0)) * PADK
                               + ((lt & 2) ? 8 : 0));
    uint32_t boff = (uint32_t)((wc * 32 + laneRow + ((lt & 2) ? 8 : 0)) * PADK
                               + ((lt & 1) ? 8 : 0));

    int row0 = tid >> 2, c4 = tid & 3;
    int row1 = row0 + 64;
    uint32_t d0 = (uint32_t)(row0 * PADK + c4 * 8) * 2;
    uint32_t d1 = (uint32_t)(row1 * PADK + c4 * 8) * 2;

    int nCh = K >> 5;

    // prefetch chunk 0 into stage 0
    {
        uint32_t sb = smB;
        size_t s0 = (size_t)row0 * K + c4 * 8;
        size_t s1 = (size_t)row1 * K + c4 * 8;
        cpa16(sb + AH_OFF*2 + d0, Ahb + s0); cpa16(sb + AH_OFF*2 + d1, Ahb + s1);
        if (TERMS == 3) {
            cpa16(sb + AL_OFF*2 + d0, Alb + s0); cpa16(sb + AL_OFF*2 + d1, Alb + s1);
        }
        cpa16(sb + BH_OFF*2 + d0, Bhb + s0); cpa16(sb + BH_OFF*2 + d1, Bhb + s1);
        cpa16(sb + BL_OFF*2 + d0, Blb + s0); cpa16(sb + BL_OFF*2 + d1, Blb + s1);
        CPA_COMMIT;
    }

    // single-sync pipeline: wait -> barrier (stage s^1 now provably free)
    //                       -> issue c+1 into s^1 -> compute c from s
    for (int c = 0; c < nCh; ++c) {
        int s = c & 1;
        CPA_WAIT(0);
        __syncthreads();
        if (c + 1 < nCh) {
            int k0 = (c + 1) << 5;
            uint32_t sb = smB + (uint32_t)(s ^ 1) * (SSTRIDE * 2);
            size_t s0 = (size_t)row0 * K + k0 + c4 * 8;
            size_t s1 = (size_t)row1 * K + k0 + c4 * 8;
            cpa16(sb + AH_OFF*2 + d0, Ahb + s0); cpa16(sb + AH_OFF*2 + d1, Ahb + s1);
            if (TERMS == 3) {
                cpa16(sb + AL_OFF*2 + d0, Alb + s0); cpa16(sb + AL_OFF*2 + d1, Alb + s1);
            }
            cpa16(sb + BH_OFF*2 + d0, Bhb + s0); cpa16(sb + BH_OFF*2 + d1, Bhb + s1);
            cpa16(sb + BL_OFF*2 + d0, Blb + s0); cpa16(sb + BL_OFF*2 + d1, Blb + s1);
            CPA_COMMIT;
        }

        uint32_t stb = smB + (uint32_t)s * (SSTRIDE * 2);
        #pragma unroll
        for (int kk = 0; kk < 32; kk += 16) {
            uint32_t ah[4][4], al[4][4], bh[4][2], bl[4][2];
            #pragma unroll
            for (int mf = 0; mf < 4; ++mf) {
                uint32_t ad = stb + 2u * (aoff + (uint32_t)(mf * 16 * PADK + kk));
                ldm4(ah[mf], ad + 2u * AH_OFF);
                if (TERMS == 3) ldm4(al[mf], ad + 2u * AL_OFF);
            }
            #pragma unroll
            for (int np = 0; np < 2; ++np) {
                uint32_t bd = stb + 2u * (boff + (uint32_t)(np * 16 * PADK + kk));
                uint32_t t4[4];
                ldm4(t4, bd + 2u * BH_OFF);
                bh[2*np][0] = t4[0]; bh[2*np][1] = t4[1];
                bh[2*np+1][0] = t4[2]; bh[2*np+1][1] = t4[3];
                ldm4(t4, bd + 2u * BL_OFF);
                bl[2*np][0] = t4[0]; bl[2*np][1] = t4[1];
                bl[2*np+1][0] = t4[2]; bl[2*np+1][1] = t4[3];
            }
            #pragma unroll
            for (int mf = 0; mf < 4; ++mf)
                #pragma unroll
                for (int nf = 0; nf < 4; ++nf) {
                    mma16816(acc[mf][nf], ah[mf], bh[nf]);
                    mma16816(acc[mf][nf], ah[mf], bl[nf]);
                    if (TERMS == 3) mma16816(acc[mf][nf], al[mf], bh[nf]);
                }
        }
    }

    // ---- epilogue ----
    if (act == 2) {
        // fused QKV: rope -> qb/kb (Q scaled to exp2 domain), transpose -> vt.
        #pragma unroll
        for (int mf = 0; mf < 4; ++mf) {
            int row = tileM + wr * 64 + mf * 16 + gid;
            #pragma unroll
            for (int nf = 0; nf < 4; ++nf) {
                int col = tileN + wc * 32 + nf * 8 + 2 * tig;
                #pragma unroll
                for (int half = 0; half < 2; ++half) {
                    int r = row + half * 8;
                    float e = acc[mf][nf][2*half];
                    float o = acc[mf][nf][2*half + 1];
                    int srow = r & (Ssz - 1);
                    if (col < Dsz) {
                        int i = (col & 63) >> 1;
                        float cv = fc[srow * 32 + i], sv = fs[srow * 32 + i];
                        float r0 = (e * cv - o * sv) * QSCL;
                        float r1 = (e * sv + o * cv) * QSCL;
                        __nv_bfloat162 p;
                        p.x = __float2bfloat16_rn(r0); p.y = __float2bfloat16_rn(r1);
                        *reinterpret_cast<__nv_bfloat162*>(qb + (size_t)r * Dsz + col) = p;
                    } else if (col < 2 * Dsz) {
                        int cc = col - Dsz;
                        int i = (cc & 63) >> 1;
                        float cv = fc[srow * 32 + i], sv = fs[srow * 32 + i];
                        float r0 = e * cv - o * sv;
                        float r1 = e * sv + o * cv;
                        __nv_bfloat162 p;
                        p.x = __float2bfloat16_rn(r0); p.y = __float2bfloat16_rn(r1);
                        *reinterpret_cast<__nv_bfloat162*>(kb + (size_t)r * Dsz + cc) = p;
                    } else {
                        int cc = col - 2 * Dsz;
                        int h = cc >> 6, n = cc & 63;
                        int bh = (r >> 11) * Hsz + h;
                        size_t base = ((size_t)bh * HDsz) * Ssz + srow;
                        vt[base + (size_t)n * Ssz]       = __float2bfloat16_rn(e);
                        vt[base + (size_t)(n + 1) * Ssz] = __float2bfloat16_rn(o);
                    }
                }
            }
        }
        return;
    }

    #pragma unroll
    for (int mf = 0; mf < 4; ++mf) {
        int row = tileM + wr * 64 + mf * 16 + gid;
        #pragma unroll
        for (int nf = 0; nf < 4; ++nf) {
            int col = tileN + wc * 32 + nf * 8 + 2 * tig;
            float2 v0 = make_float2(acc[mf][nf][0], acc[mf][nf][1]);
            float2 v1 = make_float2(acc[mf][nf][2], acc[mf][nf][3]);
            if (bias) {
                float2 bv = *reinterpret_cast<const float2*>(bias + col);
                v0.x += bv.x; v0.y += bv.y;
                v1.x += bv.x; v1.y += bv.y;
            }
            if (act == 1) {
                v0.x = gelu_exact(v0.x); v0.y = gelu_exact(v0.y);
                v1.x = gelu_exact(v1.x); v1.y = gelu_exact(v1.y);
            }
            size_t i0 = (size_t)row * N + col;
            size_t i1 = (size_t)(row + 8) * N + col;
            if (resid) {
                float2 r0 = *reinterpret_cast<const float2*>(resid + i0);
                float2 r1 = *reinterpret_cast<const float2*>(resid + i1);
                v0.x += r0.x; v0.y += r0.y;
                v1.x += r1.x; v1.y += r1.y;
            }
            if (C) {
                *reinterpret_cast<float2*>(C + i0) = v0;
                *reinterpret_cast<float2*>(C + i1) = v1;
            }
            if (Oh) {
                __nv_bfloat16 h0 = __float2bfloat16_rn(v0.x), h1 = __float2bfloat16_rn(v0.y);
                __nv_bfloat16 h2 = __float2bfloat16_rn(v1.x), h3 = __float2bfloat16_rn(v1.y);
                uint32_t uh0 = (uint32_t)__bfloat16_as_ushort(h0) | ((uint32_t)__bfloat16_as_ushort(h1) << 16);
                uint32_t uh1 = (uint32_t)__bfloat16_as_ushort(h2) | ((uint32_t)__bfloat16_as_ushort(h3) << 16);
                uint32_t ul0 = packbf(v0.x - __bfloat162float(h0), v0.y - __bfloat162float(h1));
                uint32_t ul1 = packbf(v1.x - __bfloat162float(h2), v1.y - __bfloat162float(h3));
                *reinterpret_cast<uint32_t*>(Oh + i0) = uh0;
                *reinterpret_cast<uint32_t*>(Oh + i1) = uh1;
                *reinterpret_cast<uint32_t*>(Ol + i0) = ul0;
                *reinterpret_cast<uint32_t*>(Ol + i1) = ul1;
            }
        }
    }
}

// ---------------- fused flash attention (single-sync pipeline) -------------
#define FQS 72
#define FVS 136
#define FQ_OFF 0
#define FK_OFF 9216
#define FV_OFF (9216 + 2*9216)
#define FSM_BYTES ((FV_OFF + 2*8704) * 2)

__global__ __launch_bounds__(256, 2) void flash_kernel(
    const __nv_bfloat16* __restrict__ Qb, const __nv_bfloat16* __restrict__ Kb,
    const __nv_bfloat16* __restrict__ Vt,
    __nv_bfloat16* __restrict__ ctxh, __nv_bfloat16* __restrict__ ctxl)
{
    extern __shared__ unsigned short fsm[];
    uint32_t smB = smem_u32(fsm);
    int tid = threadIdx.x, lane = tid & 31, w = tid >> 5;
    int gid = lane >> 2, tig = lane & 3;
    int laneRow = lane & 7, lt = lane >> 3;
    int tq = blockIdx.x, bh = blockIdx.y;
    int b = bh >> 4, h = bh & 15;

    size_t qRow0 = (size_t)b * Ssz + tq * 128;
    const __nv_bfloat16* Qg = Qb + qRow0 * Dsz + h * HDsz;
    const __nv_bfloat16* Kg = Kb + ((size_t)b * Ssz) * Dsz + h * HDsz;
    const __nv_bfloat16* Vg = Vt + ((size_t)bh * HDsz) * Ssz;

    #pragma unroll
    for (int i = 0; i < 4; ++i) {
        int idx = tid + i * 256; int r = idx >> 3, c = idx & 7;
        cpa16(smB + (FQ_OFF + r * FQS) * 2 + c * 16, Qg + (size_t)r * Dsz + c * 8);
    }
    #pragma unroll
    for (int i = 0; i < 4; ++i) {
        int idx = tid + i * 256; int r = idx >> 3, c = idx & 7;
        cpa16(smB + (FK_OFF + r * FQS) * 2 + c * 16, Kg + (size_t)r * Dsz + c * 8);
    }
    #pragma unroll
    for (int i = 0; i < 4; ++i) {
        int idx = tid + i * 256; int n = idx >> 4, c = idx & 15;
        cpa16(smB + (FV_OFF + n * FVS) * 2 + c * 16, Vg + (size_t)n * Ssz + c * 8);
    }
    CPA_COMMIT;

    uint32_t qoff = (uint32_t)((w * 16 + laneRow + ((lt & 1) ? 8 : 0)) * FQS
                               + ((lt & 2) ? 8 : 0));
    uint32_t koff = (uint32_t)((laneRow + ((lt & 2) ? 8 : 0)) * FQS
                               + ((lt & 1) ? 8 : 0));
    uint32_t voff = (uint32_t)((laneRow + ((lt & 2) ? 8 : 0)) * FVS
                               + ((lt & 1) ? 8 : 0));

    float m0 = -1e30f, m1 = -1e30f, l0 = 0.f, l1 = 0.f;
    float ctx[8][4];
    #pragma unroll
    for (int nf = 0; nf < 8; ++nf)
        #pragma unroll
        for (int i = 0; i < 4; ++i) ctx[nf][i] = 0.f;

    int st = 0;
    for (int t = 0; t < 16; ++t) {
        CPA_WAIT(0);
        __syncthreads();       // stage st^1 now provably free (all read it at t-1)
        if (t + 1 < 16) {
            int s2 = st ^ 1;
            #pragma unroll
            for (int i = 0; i < 4; ++i) {
                int idx = tid + i * 256; int r = idx >> 3, c = idx & 7;
                cpa16(smB + (FK_OFF + s2 * 9216 + r * FQS) * 2 + c * 16,
                      Kg + ((size_t)((t + 1) * 128 + r)) * Dsz + c * 8);
            }
            #pragma unroll
            for (int i = 0; i < 4; ++i) {
                int idx = tid + i * 256; int n = idx >> 4, c = idx & 15;
                cpa16(smB + (FV_OFF + s2 * 8704 + n * FVS) * 2 + c * 16,
                      Vg + (size_t)n * Ssz + (t + 1) * 128 + c * 8);
            }
            CPA_COMMIT;
        }

        uint32_t Qsb = smB + FQ_OFF * 2;
        uint32_t Ksb = smB + (FK_OFF + st * 9216) * 2;
        uint32_t Vsb = smB + (FV_OFF + st * 8704) * 2;

        // ---- S = Q K^T (scores already in log2 domain via QSCL) ----
        float s4[16][4];
        #pragma unroll
        for (int nf = 0; nf < 16; ++nf)
            #pragma unroll
            for (int i = 0; i < 4; ++i) s4[nf][i] = 0.f;

        #pragma unroll
        for (int kk = 0; kk < 64; kk += 16) {
            uint32_t a[4];
            ldm4(a, Qsb + 2u * (qoff + kk));
            #pragma unroll
            for (int np = 0; np < 8; ++np) {
                uint32_t t4[4];
                ldm4(t4, Ksb + 2u * (koff + (uint32_t)(np * 16 * FQS + kk)));
                mma16816(s4[2*np],     a, t4);
                mma16816(s4[2*np + 1], a, t4 + 2);
            }
        }

        // ---- online softmax (exp2 domain) ----
        float mx0 = -1e30f, mx1 = -1e30f;
        #pragma unroll
        for (int nf = 0; nf < 16; ++nf) {
            mx0 = fmaxf(mx0, fmaxf(s4[nf][0], s4[nf][1]));
            mx1 = fmaxf(mx1, fmaxf(s4[nf][2], s4[nf][3]));
        }
        mx0 = fmaxf(mx0, __shfl_xor_sync(0xffffffffu, mx0, 1));
        mx0 = fmaxf(mx0, __shfl_xor_sync(0xffffffffu, mx0, 2));
        mx1 = fmaxf(mx1, __shfl_xor_sync(0xffffffffu, mx1, 1));
        mx1 = fmaxf(mx1, __shfl_xor_sync(0xffffffffu, mx1, 2));
        float mn0 = fmaxf(m0, mx0), mn1 = fmaxf(m1, mx1);
        float al0 = exp2f(m0 - mn0), al1 = exp2f(m1 - mn1);
        float sum0 = 0.f, sum1 = 0.f;
        #pragma unroll
        for (int nf = 0; nf < 16; ++nf) {
            s4[nf][0] = exp2f(s4[nf][0] - mn0);
            s4[nf][1] = exp2f(s4[nf][1] - mn0);
            s4[nf][2] = exp2f(s4[nf][2] - mn1);
            s4[nf][3] = exp2f(s4[nf][3] - mn1);
            sum0 += s4[nf][0] + s4[nf][1];
            sum1 += s4[nf][2] + s4[nf][3];
        }
        sum0 += __shfl_xor_sync(0xffffffffu, sum0, 1);
        sum0 += __shfl_xor_sync(0xffffffffu, sum0, 2);
        sum1 += __shfl_xor_sync(0xffffffffu, sum1, 1);
        sum1 += __shfl_xor_sync(0xffffffffu, sum1, 2);
        l0 = l0 * al0 + sum0; l1 = l1 * al1 + sum1;
        m0 = mn0; m1 = mn1;
        #pragma unroll
        for (int nf = 0; nf < 8; ++nf) {
            ctx[nf][0] *= al0; ctx[nf][1] *= al0;
            ctx[nf][2] *= al1; ctx[nf][3] *= al1;
        }

        // ---- ctx += P @ V ----
        #pragma unroll
        for (int kc = 0; kc < 8; ++kc) {
            uint32_t a[4];
            a[0] = packbf(s4[2*kc][0],   s4[2*kc][1]);
            a[1] = packbf(s4[2*kc][2],   s4[2*kc][3]);
            a[2] = packbf(s4[2*kc+1][0], s4[2*kc+1][1]);
            a[3] = packbf(s4[2*kc+1][2], s4[2*kc+1][3]);
            #pragma unroll
            for (int np = 0; np < 4; ++np) {
                uint32_t t4[4];
                ldm4(t4, Vsb + 2u * (voff + (uint32_t)(np * 16 * FVS + kc * 16)));
                mma16816(ctx[2*np],     a, t4);
                mma16816(ctx[2*np + 1], a, t4 + 2);
            }
        }

        st ^= 1;
    }

    float i0 = 1.f / l0, i1 = 1.f / l1;
    size_t rbase = (qRow0 + w * 16 + gid) * Dsz + h * HDsz;
    #pragma unroll
    for (int nf = 0; nf < 8; ++nf) {
        int col = nf * 8 + 2 * tig;
        float v00 = ctx[nf][0] * i0, v01 = ctx[nf][1] * i0;
        float v10 = ctx[nf][2] * i1, v11 = ctx[nf][3] * i1;
        __nv_bfloat16 h00 = __float2bfloat16_rn(v00), h01 = __float2bfloat16_rn(v01);
        __nv_bfloat16 h10 = __float2bfloat16_rn(v10), h11 = __float2bfloat16_rn(v11);
        uint32_t uh0 = (uint32_t)__bfloat16_as_ushort(h00) | ((uint32_t)__bfloat16_as_ushort(h01) << 16);
        uint32_t uh1 = (uint32_t)__bfloat16_as_ushort(h10) | ((uint32_t)__bfloat16_as_ushort(h11) << 16);
        uint32_t ul0 = packbf(v00 - __bfloat162float(h00), v01 - __bfloat162float(h01));
        uint32_t ul1 = packbf(v10 - __bfloat162float(h10), v11 - __bfloat162float(h11));
        *reinterpret_cast<uint32_t*>(ctxh + rbase + col) = uh0;
        *reinterpret_cast<uint32_t*>(ctxh + rbase + (size_t)8 * Dsz + col) = uh1;
        *reinterpret_cast<uint32_t*>(ctxl + rbase + col) = ul0;
        *reinterpret_cast<uint32_t*>(ctxl + rbase + (size_t)8 * Dsz + col) = ul1;
    }
}

// ---------------- launch ----------------------------------------------------
extern "C" void kernel_launch(void* const* d_in, const int* in_sizes, int n_in,
                              void* d_out, int out_size)
{
    const float* x    = (const float*)d_in[0];
    const float* fc   = (const float*)d_in[2];
    const float* fs   = (const float*)d_in[3];
    const float* Wq   = (const float*)d_in[4];
    const float* Wk   = (const float*)d_in[5];
    const float* Wv   = (const float*)d_in[6];
    const float* Wo   = (const float*)d_in[7];
    const float* bo   = (const float*)d_in[8];
    const float* ln1g = (const float*)d_in[9];
    const float* ln1b = (const float*)d_in[10];
    const float* ln2g = (const float*)d_in[11];
    const float* ln2b = (const float*)d_in[12];
    const float* W1   = (const float*)d_in[13];
    const float* b1   = (const float*)d_in[14];
    const float* W2   = (const float*)d_in[15];
    const float* b2   = (const float*)d_in[16];
    float* out = (float*)d_out;

    float *x1;
    cudaGetSymbolAddress((void**)&x1, g_x1);

    __nv_bfloat16 *xnh,*xnl,*xn2h,*xn2l,*ctxh,*ctxl,*hh,*hl,*qb,*kb,*vt;
    cudaGetSymbolAddress((void**)&xnh,  g_xnh);  cudaGetSymbolAddress((void**)&xnl,  g_xnl);
    cudaGetSymbolAddress((void**)&xn2h, g_xn2h); cudaGetSymbolAddress((void**)&xn2l, g_xn2l);
    cudaGetSymbolAddress((void**)&ctxh, g_ctxh); cudaGetSymbolAddress((void**)&ctxl, g_ctxl);
    cudaGetSymbolAddress((void**)&hh,   g_hh);   cudaGetSymbolAddress((void**)&hl,   g_hl);
    cudaGetSymbolAddress((void**)&qb,   g_qb);
    cudaGetSymbolAddress((void**)&kb,   g_kb);
    cudaGetSymbolAddress((void**)&vt,   g_vt);

    __nv_bfloat16 *wqkvh,*wqkvl,*woh,*wol,*w1h,*w1l,*w2h,*w2l;
    cudaGetSymbolAddress((void**)&wqkvh, g_wqkv_h); cudaGetSymbolAddress((void**)&wqkvl, g_wqkv_l);
    cudaGetSymbolAddress((void**)&woh, g_wo_h); cudaGetSymbolAddress((void**)&wol, g_wo_l);
    cudaGetSymbolAddress((void**)&w1h, g_w1_h); cudaGetSymbolAddress((void**)&w1l, g_w1_l);
    cudaGetSymbolAddress((void**)&w2h, g_w2_h); cudaGetSymbolAddress((void**)&w2l, g_w2_l);

    cudaFuncSetAttribute(bgemm<2>, cudaFuncAttributeMaxDynamicSharedMemorySize, BG_SMEM);
    cudaFuncSetAttribute(bgemm<3>, cudaFuncAttributeMaxDynamicSharedMemorySize, BG_SMEM);
    cudaFuncSetAttribute(flash_kernel, cudaFuncAttributeMaxDynamicSharedMemorySize, FSM_BYTES);

    // 0. all weight conversions in one launch
    wconv_all_kernel<<<12288, 256>>>(Wq, Wk, Wv, Wo, W1, W2,
                                     wqkvh, wqkvl, woh, wol, w1h, w1l, w2h, w2l);

    // 1. LN1 -> bf16 hi/lo
    ln_bf_kernel<<<ROWS, 256>>>(x, ln1g, ln1b, xnh, xnl);

    // 2. fused QKV projection (2-term)
    dim3 gQKV(3*Dsz/128, ROWS/128);
    bgemm<2><<<gQKV, 256, BG_SMEM>>>(xnh, xnl, wqkvh, wqkvl, nullptr, nullptr, nullptr,
                                     Dsz, 3*Dsz, nullptr, nullptr, 2, fc, fs, qb, kb, vt);

    // 3-6. flash attention -> ctx hi/lo
    flash_kernel<<<dim3(Ssz/128, Bsz*Hsz), 256, FSM_BYTES>>>(qb, kb, vt, ctxh, ctxl);

    // 7. x1 = x + ctx @ Wo + bo (2-term)
    dim3 gQ(Dsz / 128, ROWS / 128);
    bgemm<2><<<gQ, 256, BG_SMEM>>>(ctxh, ctxl, woh, wol, x1, nullptr, nullptr,
                                   Dsz, Dsz, bo, x, 0, nullptr, nullptr, nullptr, nullptr, nullptr);

    // 8. LN2 -> bf16 hi/lo
    ln_bf_kernel<<<ROWS, 256>>>(x1, ln2g, ln2b, xn2h, xn2l);

    // 9. h = gelu(xn2 @ W1 + b1) -> bf16 hi/lo  (3-term: FFN path needs precision)
    dim3 gF1(DFFsz / 128, ROWS / 128);
    bgemm<3><<<gF1, 256, BG_SMEM>>>(xn2h, xn2l, w1h, w1l, nullptr, hh, hl,
                                    Dsz, DFFsz, b1, nullptr, 1, nullptr, nullptr, nullptr, nullptr, nullptr);

    // 10. out = x1 + h @ W2 + b2  (3-term)
    bgemm<3><<<gQ, 256, BG_SMEM>>>(hh, hl, w2h, w2l, out, nullptr, nullptr,
                                   DFFsz, Dsz, b2, x1, 0, nullptr, nullptr, nullptr, nullptr, nullptr);
}